// round 2
// baseline (speedup 1.0000x reference)
#include <cuda_runtime.h>

// Problem constants
#define BB   8
#define NN   2048
#define DIMM 1024
#define HH   16
#define DHH  64
#define MM   (BB*NN)          // 16384 rows
#define EPSF 1e-6f

// ---------------------------------------------------------------------------
// Scratch (device globals; no allocation allowed)
// ---------------------------------------------------------------------------
__device__ float g_qlin[BB*NN*DIMM];
__device__ float g_klin[BB*NN*DIMM];
__device__ float g_vlin[BB*NN*DIMM];
__device__ float g_q[BB*NN*DIMM];
__device__ float g_k[BB*NN*DIMM];
__device__ float g_v[BB*NN*DIMM];
__device__ float g_O[BB*NN*DIMM];
__device__ float g_a[BB*NN*HH];
__device__ float g_bg[BB*NN*HH];

__device__ __forceinline__ float sigmoidf_(float x) { return 1.f / (1.f + __expf(-x)); }
__device__ __forceinline__ float siluf_(float x)    { return x / (1.f + __expf(-x)); }

// ---------------------------------------------------------------------------
// GEMM: C[m,n] = act( sum_k A[m,k] * W[n,k] + bias[n] )
// A: (M,1024) row-major, W: (1024,1024) row-major (n-th row = weights of out n)
// BM=BN=128, BK=8, 256 threads, 8x8 microtile with split-64 column mapping so
// stores are float4-coalesced.
// CSEL: 0->g_qlin 1->g_klin 2->g_vlin 3->param Cout.  AFROM_O: A = g_O.
// ---------------------------------------------------------------------------
template<int CSEL, bool SILU, bool AFROM_O>
__global__ __launch_bounds__(256, 2)
void gemm_kernel(const float* __restrict__ Ain, const float* __restrict__ W,
                 const float* __restrict__ bias, float* __restrict__ Cout)
{
    const float* __restrict__ A = AFROM_O ? g_O : Ain;
    float* __restrict__ C = (CSEL == 0) ? g_qlin : (CSEL == 1) ? g_klin
                           : (CSEL == 2) ? g_vlin : Cout;

    __shared__ float As[8][128];
    __shared__ float Bs[8][128];

    const int bm = blockIdx.y * 128;
    const int bn = blockIdx.x * 128;
    const int tid = threadIdx.x;

    const int lrow = tid >> 1;          // 0..127
    const int lcol = (tid & 1) * 4;     // 0 or 4
    const float* Aptr = A + (size_t)(bm + lrow) * DIMM + lcol;
    const float* Wptr = W + (size_t)(bn + lrow) * DIMM + lcol;

    const int tx = tid & 15;
    const int ty = tid >> 4;

    float acc[8][8];
#pragma unroll
    for (int i = 0; i < 8; i++)
#pragma unroll
        for (int j = 0; j < 8; j++) acc[i][j] = 0.f;

    for (int k0 = 0; k0 < DIMM; k0 += 8) {
        float4 av = *(const float4*)(Aptr + k0);
        float4 bv = *(const float4*)(Wptr + k0);
        As[lcol + 0][lrow] = av.x; As[lcol + 1][lrow] = av.y;
        As[lcol + 2][lrow] = av.z; As[lcol + 3][lrow] = av.w;
        Bs[lcol + 0][lrow] = bv.x; Bs[lcol + 1][lrow] = bv.y;
        Bs[lcol + 2][lrow] = bv.z; Bs[lcol + 3][lrow] = bv.w;
        __syncthreads();

#pragma unroll
        for (int kk = 0; kk < 8; kk++) {
            float af[8], bf[8];
            float4 a0 = *(const float4*)&As[kk][ty * 4];
            float4 a1 = *(const float4*)&As[kk][64 + ty * 4];
            float4 b0 = *(const float4*)&Bs[kk][tx * 4];
            float4 b1 = *(const float4*)&Bs[kk][64 + tx * 4];
            af[0]=a0.x; af[1]=a0.y; af[2]=a0.z; af[3]=a0.w;
            af[4]=a1.x; af[5]=a1.y; af[6]=a1.z; af[7]=a1.w;
            bf[0]=b0.x; bf[1]=b0.y; bf[2]=b0.z; bf[3]=b0.w;
            bf[4]=b1.x; bf[5]=b1.y; bf[6]=b1.z; bf[7]=b1.w;
#pragma unroll
            for (int i = 0; i < 8; i++)
#pragma unroll
                for (int j = 0; j < 8; j++)
                    acc[i][j] += af[i] * bf[j];
        }
        __syncthreads();
    }

    // epilogue: rows = bm + ii*64 + ty*4 + i ; cols = bn + jj*64 + tx*4 + j
#pragma unroll
    for (int ii = 0; ii < 2; ii++) {
#pragma unroll
        for (int i = 0; i < 4; i++) {
            int row = bm + ii * 64 + ty * 4 + i;
#pragma unroll
            for (int jj = 0; jj < 2; jj++) {
                int col = bn + jj * 64 + tx * 4;
                float4 bsv = *(const float4*)(bias + col);
                float4 o;
                o.x = acc[ii*4+i][jj*4+0] + bsv.x;
                o.y = acc[ii*4+i][jj*4+1] + bsv.y;
                o.z = acc[ii*4+i][jj*4+2] + bsv.z;
                o.w = acc[ii*4+i][jj*4+3] + bsv.w;
                if (SILU) {
                    o.x = siluf_(o.x); o.y = siluf_(o.y);
                    o.z = siluf_(o.z); o.w = siluf_(o.w);
                }
                *(float4*)(C + (size_t)row * DIMM + col) = o;
            }
        }
    }
}

// ---------------------------------------------------------------------------
// Gate projections: a = sigmoid(x @ Wa^T + ba), b = sigmoid(x @ Wb^T + bb)
// One block per row (b*N+t). 256 threads: 32 outputs x 8 partial lanes.
// ---------------------------------------------------------------------------
__global__ __launch_bounds__(256)
void gate_kernel(const float* __restrict__ x,
                 const float* __restrict__ Wa, const float* __restrict__ ba,
                 const float* __restrict__ Wb, const float* __restrict__ bb)
{
    __shared__ float xs[DIMM];
    const int row = blockIdx.x;
    const float* xr = x + (size_t)row * DIMM;
    const int tid = threadIdx.x;

    ((float4*)xs)[tid] = ((const float4*)xr)[tid];   // 256 * 16B = 4KB
    __syncthreads();

    const int o = tid >> 3;       // 0..31 (0..15 -> a, 16..31 -> b)
    const int sub = tid & 7;
    const int h = o & 15;
    const float* Wp = ((o < 16) ? Wa : Wb) + (size_t)h * DIMM;

    float s = 0.f;
#pragma unroll 8
    for (int i = 0; i < 128; i++) {
        int c = sub + 8 * i;
        s += xs[c] * Wp[c];
    }
    s += __shfl_down_sync(0xffffffffu, s, 4);
    s += __shfl_down_sync(0xffffffffu, s, 2);
    s += __shfl_down_sync(0xffffffffu, s, 1);
    if (sub == 0) {
        float bi = (o < 16) ? ba[h] : bb[h];
        float r = sigmoidf_(s + bi);
        float* dst = (o < 16) ? g_a : g_bg;
        dst[(size_t)row * HH + h] = r;
    }
}

// ---------------------------------------------------------------------------
// Depthwise conv (K=4, pad=2, output truncated to N) + SiLU + optional L2 norm
// grid: (B*N, 3)  z=0:q(norm) 1:k(norm) 2:v(no norm).  256 threads, 4 ch each.
// y[b,t,c] = silu( sum_{j=0..3} lin[b, t+j-2, c] * w[c*4+j] )
// ---------------------------------------------------------------------------
__global__ __launch_bounds__(256)
void conv_norm_kernel(const float* __restrict__ wq, const float* __restrict__ wk,
                      const float* __restrict__ wv)
{
    const int z = blockIdx.y;
    const float* __restrict__ in  = (z == 0) ? g_qlin : (z == 1) ? g_klin : g_vlin;
    const float* __restrict__ w   = (z == 0) ? wq     : (z == 1) ? wk     : wv;
    float* __restrict__ out       = (z == 0) ? g_q    : (z == 1) ? g_k    : g_v;

    const int bt = blockIdx.x;
    const int b = bt / NN;
    const int t = bt % NN;
    const int tid = threadIdx.x;
    const int c0 = tid * 4;

    // per-thread weights: 16 consecutive floats w[c0*4 .. c0*4+15]
    float4 w0 = *(const float4*)(w + c0 * 4 + 0);
    float4 w1 = *(const float4*)(w + c0 * 4 + 4);
    float4 w2 = *(const float4*)(w + c0 * 4 + 8);
    float4 w3 = *(const float4*)(w + c0 * 4 + 12);
    // wc[m] = taps for channel c0+m
    float wc[4][4] = {{w0.x,w0.y,w0.z,w0.w},{w1.x,w1.y,w1.z,w1.w},
                      {w2.x,w2.y,w2.z,w2.w},{w3.x,w3.y,w3.z,w3.w}};

    float y[4] = {0.f, 0.f, 0.f, 0.f};
#pragma unroll
    for (int j = 0; j < 4; j++) {
        int tt = t + j - 2;
        if (tt >= 0 && tt < NN) {
            float4 xv = *(const float4*)(in + ((size_t)b * NN + tt) * DIMM + c0);
            y[0] += xv.x * wc[0][j];
            y[1] += xv.y * wc[1][j];
            y[2] += xv.z * wc[2][j];
            y[3] += xv.w * wc[3][j];
        }
    }
#pragma unroll
    for (int m = 0; m < 4; m++) y[m] = siluf_(y[m]);

    // block reduction of sum of squares (used only for z<2)
    float ss = y[0]*y[0] + y[1]*y[1] + y[2]*y[2] + y[3]*y[3];
#pragma unroll
    for (int off = 16; off; off >>= 1) ss += __shfl_down_sync(0xffffffffu, ss, off);
    __shared__ float wss[8];
    __shared__ float inv_sh;
    const int lane = tid & 31, wid = tid >> 5;
    if (lane == 0) wss[wid] = ss;
    __syncthreads();
    if (tid == 0) {
        float tot = 0.f;
#pragma unroll
        for (int i = 0; i < 8; i++) tot += wss[i];
        inv_sh = 1.f / (sqrtf(tot) + EPSF);
    }
    __syncthreads();
    float inv = (z < 2) ? inv_sh : 1.f;

    float4 ov; ov.x = y[0]*inv; ov.y = y[1]*inv; ov.z = y[2]*inv; ov.w = y[3]*inv;
    *(float4*)(out + ((size_t)b * NN + t) * DIMM + c0) = ov;
}

// ---------------------------------------------------------------------------
// Gated delta-rule scan. One block per (b,h); 64 threads; thread d owns row
// S[d][0..63] in registers.
//   Sk_d     = sum_e S[d][e] k[e]
//   coef_d   = b*v_d - a*b*Sk_d
//   S[d][e]  = a*S[d][e] + coef_d*k[e]
//   o_e      = sum_d q_d * S_new[d][e]   (shared-memory transpose reduce)
// q/k/v/a/b for step t+1 are prefetched during step t.
// ---------------------------------------------------------------------------
__global__ __launch_bounds__(64)
void scan_kernel()
{
    const int bh = blockIdx.x;
    const int b = bh >> 4;
    const int h = bh & 15;
    const int d = threadIdx.x;

    __shared__ float k_sh[64];
    __shared__ float p_sh[64][65];   // p_sh[e][d] = q_d * S_new[d][e]

    float S[64];
#pragma unroll
    for (int e = 0; e < 64; e++) S[e] = 0.f;

    const size_t base  = ((size_t)b * NN) * DIMM + h * DHH + d;  // [b, t, h*64+d]
    const size_t gbase = ((size_t)b * NN) * HH + h;              // [b, t, h]

    float kd = g_k[base];
    float qd = g_q[base];
    float vd = g_v[base];
    float av = g_a[gbase];
    float bv = g_bg[gbase];

    for (int t = 0; t < NN; t++) {
        k_sh[d] = kd;
        __syncthreads();

        // prefetch next step
        float kn = 0.f, qn = 0.f, vn = 0.f, an = 0.f, bn = 0.f;
        if (t + 1 < NN) {
            size_t o = base + (size_t)(t + 1) * DIMM;
            kn = g_k[o]; qn = g_q[o]; vn = g_v[o];
            size_t go = gbase + (size_t)(t + 1) * HH;
            an = g_a[go]; bn = g_bg[go];
        }

        float sk0 = 0.f, sk1 = 0.f, sk2 = 0.f, sk3 = 0.f;
#pragma unroll
        for (int e = 0; e < 64; e += 4) {
            sk0 += S[e + 0] * k_sh[e + 0];
            sk1 += S[e + 1] * k_sh[e + 1];
            sk2 += S[e + 2] * k_sh[e + 2];
            sk3 += S[e + 3] * k_sh[e + 3];
        }
        float sk = (sk0 + sk1) + (sk2 + sk3);
        float coef = bv * vd - av * bv * sk;

#pragma unroll
        for (int e = 0; e < 64; e++) {
            S[e] = av * S[e] + coef * k_sh[e];
            p_sh[e][d] = qd * S[e];
        }
        __syncthreads();

        // thread d reduces column e = d of p (row read, conflict-free via pad)
        float o0 = 0.f, o1 = 0.f, o2 = 0.f, o3 = 0.f;
#pragma unroll
        for (int r = 0; r < 64; r += 4) {
            o0 += p_sh[d][r + 0];
            o1 += p_sh[d][r + 1];
            o2 += p_sh[d][r + 2];
            o3 += p_sh[d][r + 3];
        }
        g_O[base + (size_t)t * DIMM] = (o0 + o1) + (o2 + o3);
        __syncthreads();   // protect k_sh / p_sh for next iteration

        kd = kn; qd = qn; vd = vn; av = an; bv = bn;
    }
}

// ---------------------------------------------------------------------------
// Launch
// ---------------------------------------------------------------------------
extern "C" void kernel_launch(void* const* d_in, const int* in_sizes, int n_in,
                              void* d_out, int out_size)
{
    (void)in_sizes; (void)n_in; (void)out_size;
    const float* x      = (const float*)d_in[0];
    const float* Wq     = (const float*)d_in[1];
    const float* bq     = (const float*)d_in[2];
    const float* Wk     = (const float*)d_in[3];
    const float* bk     = (const float*)d_in[4];
    const float* Wv     = (const float*)d_in[5];
    const float* bv     = (const float*)d_in[6];
    const float* Wa     = (const float*)d_in[7];
    const float* ba     = (const float*)d_in[8];
    const float* Wb     = (const float*)d_in[9];
    const float* bb     = (const float*)d_in[10];
    const float* conv_q = (const float*)d_in[11];
    const float* conv_k = (const float*)d_in[12];
    const float* conv_v = (const float*)d_in[13];
    const float* Wo     = (const float*)d_in[14];
    const float* bo     = (const float*)d_in[15];
    float* out = (float*)d_out;

    dim3 ggrid(DIMM / 128, MM / 128);   // (8, 128)

    gemm_kernel<0, true,  false><<<ggrid, 256>>>(x, Wq, bq, nullptr);
    gemm_kernel<1, true,  false><<<ggrid, 256>>>(x, Wk, bk, nullptr);
    gemm_kernel<2, true,  false><<<ggrid, 256>>>(x, Wv, bv, nullptr);

    gate_kernel<<<MM, 256>>>(x, Wa, ba, Wb, bb);

    conv_norm_kernel<<<dim3(MM, 3), 256>>>(conv_q, conv_k, conv_v);

    scan_kernel<<<BB * HH, 64>>>();

    gemm_kernel<3, false, true><<<ggrid, 256>>>(nullptr, Wo, bo, out);
}

// round 4
// speedup vs baseline: 1.7111x; 1.7111x over previous
#include <cuda_runtime.h>
#include <cuda_bf16.h>
#include <cstdint>

// Problem constants
#define BB   8
#define NN   2048
#define DIMM 1024
#define HH   16
#define DHH  64
#define MM   (BB*NN)          // 16384 rows
#define EPSF 1e-6f

// ---------------------------------------------------------------------------
// Scratch (device globals; no allocation allowed)
// ---------------------------------------------------------------------------
__device__ float g_qlin[BB*NN*DIMM];
__device__ float g_klin[BB*NN*DIMM];
__device__ float g_vlin[BB*NN*DIMM];
__device__ float g_q[BB*NN*DIMM];
__device__ float g_k[BB*NN*DIMM];
__device__ float g_v[BB*NN*DIMM];
__device__ float g_O[BB*NN*DIMM];
__device__ float g_a[BB*NN*HH];
__device__ float g_bg[BB*NN*HH];

// bf16 split operands
__device__ __nv_bfloat16 g_xhi[BB*NN*DIMM];
__device__ __nv_bfloat16 g_xlo[BB*NN*DIMM];
__device__ __nv_bfloat16 g_ohi[BB*NN*DIMM];
__device__ __nv_bfloat16 g_olo[BB*NN*DIMM];
__device__ __nv_bfloat16 g_wq_hi[DIMM*DIMM];
__device__ __nv_bfloat16 g_wq_lo[DIMM*DIMM];
__device__ __nv_bfloat16 g_wk_hi[DIMM*DIMM];
__device__ __nv_bfloat16 g_wk_lo[DIMM*DIMM];
__device__ __nv_bfloat16 g_wv_hi[DIMM*DIMM];
__device__ __nv_bfloat16 g_wv_lo[DIMM*DIMM];
__device__ __nv_bfloat16 g_wo_hi[DIMM*DIMM];
__device__ __nv_bfloat16 g_wo_lo[DIMM*DIMM];
__device__ __nv_bfloat16 g_wab_hi[32*DIMM];
__device__ __nv_bfloat16 g_wab_lo[32*DIMM];

__device__ __forceinline__ float sigmoidf_(float x) { return 1.f / (1.f + __expf(-x)); }
__device__ __forceinline__ float siluf_(float x)    { return x / (1.f + __expf(-x)); }

// ---------------------------------------------------------------------------
// PTX helpers (sm_80-era ISA only: cp.async, ldmatrix, mma.sync)
// ---------------------------------------------------------------------------
__device__ __forceinline__ uint32_t smem_u32(const void* p) {
    uint32_t a;
    asm("{ .reg .u64 t; cvta.to.shared.u64 t, %1; cvt.u32.u64 %0, t; }" : "=r"(a) : "l"(p));
    return a;
}
#define SWZ128(o) ((o) ^ (((o) >> 3) & 0x70))

__device__ __forceinline__ void cp_async16(uint32_t dst, const void* src) {
    asm volatile("cp.async.ca.shared.global [%0], [%1], 16;\n" :: "r"(dst), "l"(src));
}
#define CP_COMMIT() asm volatile("cp.async.commit_group;\n" ::: "memory")
#define CP_WAIT1()  asm volatile("cp.async.wait_group 1;\n" ::: "memory")
#define CP_WAIT0()  asm volatile("cp.async.wait_group 0;\n" ::: "memory")

__device__ __forceinline__ void ldsm4(uint32_t* r, uint32_t addr) {
    asm volatile("ldmatrix.sync.aligned.m8n8.x4.shared.b16 {%0,%1,%2,%3}, [%4];"
                 : "=r"(r[0]), "=r"(r[1]), "=r"(r[2]), "=r"(r[3]) : "r"(addr));
}
__device__ __forceinline__ void mma_bf16(float* d, const uint32_t* a, const uint32_t* b) {
    asm volatile(
        "mma.sync.aligned.m16n8k16.row.col.f32.bf16.bf16.f32 "
        "{%0,%1,%2,%3}, {%4,%5,%6,%7}, {%8,%9}, {%0,%1,%2,%3};"
        : "+f"(d[0]), "+f"(d[1]), "+f"(d[2]), "+f"(d[3])
        : "r"(a[0]), "r"(a[1]), "r"(a[2]), "r"(a[3]), "r"(b[0]), "r"(b[1]));
}

// ---------------------------------------------------------------------------
// Split conversion: hi = bf16(v), lo = bf16(v - hi). 4 elems/thread.
// ---------------------------------------------------------------------------
__global__ __launch_bounds__(256)
void cvt_pair_kernel(const float* __restrict__ src, __nv_bfloat16* __restrict__ hi,
                     __nv_bfloat16* __restrict__ lo, int n4)
{
    int i = blockIdx.x * blockDim.x + threadIdx.x;
    if (i >= n4) return;
    float4 v = ((const float4*)src)[i];
    __nv_bfloat16 h0 = __float2bfloat16(v.x), h1 = __float2bfloat16(v.y);
    __nv_bfloat16 h2 = __float2bfloat16(v.z), h3 = __float2bfloat16(v.w);
    __nv_bfloat16 l0 = __float2bfloat16(v.x - __bfloat162float(h0));
    __nv_bfloat16 l1 = __float2bfloat16(v.y - __bfloat162float(h1));
    __nv_bfloat16 l2 = __float2bfloat16(v.z - __bfloat162float(h2));
    __nv_bfloat16 l3 = __float2bfloat16(v.w - __bfloat162float(h3));
    uint2 hv, lv;
    hv.x = (uint32_t)__bfloat16_as_ushort(h0) | ((uint32_t)__bfloat16_as_ushort(h1) << 16);
    hv.y = (uint32_t)__bfloat16_as_ushort(h2) | ((uint32_t)__bfloat16_as_ushort(h3) << 16);
    lv.x = (uint32_t)__bfloat16_as_ushort(l0) | ((uint32_t)__bfloat16_as_ushort(l1) << 16);
    lv.y = (uint32_t)__bfloat16_as_ushort(l2) | ((uint32_t)__bfloat16_as_ushort(l3) << 16);
    ((uint2*)hi)[i] = hv;
    ((uint2*)lo)[i] = lv;
}

// ---------------------------------------------------------------------------
// HMMA (mma.sync) bf16-split GEMM.
// C[m,n] = act( sum_k A[m,k]*W[n,k] + bias[n] )  via Ahi*Whi + Ahi*Wlo + Alo*Whi.
// BM=128, BN template (128 / 32). K chunk = 64 bf16, 2-stage cp.async pipeline.
// A row-major k-contig, W n-major k-contig == "col" operand of row.col mma.
// CSEL: 0 g_qlin, 1 g_klin, 2 g_vlin, 3 param C.  ACT: 0 none, 1 silu, 2 gates.
// ---------------------------------------------------------------------------
template<int ROWS>
__device__ __forceinline__ void load_tile(uint32_t dst, const __nv_bfloat16* __restrict__ g,
                                          int row0, int k0, int tid)
{
    constexpr int ITERS = ROWS * 8 / 256;
#pragma unroll
    for (int i = 0; i < ITERS; i++) {
        int sidx = tid + i * 256;
        int r = sidx >> 3, s = sidx & 7;
        cp_async16(dst + SWZ128(r * 128 + s * 16),
                   g + ((size_t)(row0 + r) * DIMM + k0 + s * 8));
    }
}

template<int BN, int ACT, int CSEL>
__global__ __launch_bounds__(256, 1)
void hmma_gemm(const __nv_bfloat16* __restrict__ Ahi, const __nv_bfloat16* __restrict__ Alo,
               const __nv_bfloat16* __restrict__ Bhi, const __nv_bfloat16* __restrict__ Blo,
               const float* __restrict__ bias, const float* __restrict__ bias2,
               float* __restrict__ Cparam)
{
    extern __shared__ char smraw[];
    uint32_t base = (smem_u32(smraw) + 1023u) & ~1023u;

    constexpr int ATILE = 128 * 128;           // bytes per A operand tile
    constexpr int BTILE = BN * 128;
    constexpr int STG   = 2 * ATILE + 2 * BTILE;
    constexpr int MT    = (BN == 128) ? 2 : 1; // m16 tiles per warp
    constexpr int NT    = (BN == 128) ? 8 : 4; // n8 frags per warp
    constexpr int WMW   = (BN == 128) ? 4 : 8; // warps along m

    const int tid = threadIdx.x;
    const int wid = tid >> 5;
    const int lid = tid & 31;
    const int bm = blockIdx.y * 128;
    const int bn = blockIdx.x * BN;

    const int warp_m0 = (wid % WMW) * (MT * 16);
    const int warp_n0 = (wid / WMW) * (NT * 8);

    // per-lane ldmatrix row/col selectors (canonical fragment mappings)
    const int a_row = lid & 15;                // m within 16
    const int a_sel = lid >> 4;                // k half (8-col block)
    const int b_row = (lid & 7) + ((lid >> 4) << 3);  // n within 16
    const int b_sel = (lid >> 3) & 1;          // k half

    // prologue: chunk0 -> stage0, chunk1 -> stage1
#pragma unroll
    for (int c = 0; c < 2; c++) {
        uint32_t st = base + c * STG;
        int k0 = c * 64;
        load_tile<128>(st,                     Ahi, bm, k0, tid);
        load_tile<128>(st + ATILE,             Alo, bm, k0, tid);
        load_tile<BN >(st + 2 * ATILE,         Bhi, bn, k0, tid);
        load_tile<BN >(st + 2 * ATILE + BTILE, Blo, bn, k0, tid);
        CP_COMMIT();
    }

    float acc[MT][NT][4];
#pragma unroll
    for (int mi = 0; mi < MT; mi++)
#pragma unroll
        for (int ni = 0; ni < NT; ni++)
#pragma unroll
            for (int j = 0; j < 4; j++) acc[mi][ni][j] = 0.f;

    for (int c = 0; c < 16; c++) {
        const int s = c & 1;
        const uint32_t st = base + s * STG;
        if (c == 15) CP_WAIT0(); else CP_WAIT1();
        __syncthreads();

        const uint32_t sAh = st, sAl = st + ATILE;
        const uint32_t sBh = st + 2 * ATILE, sBl = st + 2 * ATILE + BTILE;

#pragma unroll
        for (int ks = 0; ks < 4; ks++) {
            uint32_t ah[MT][4], al[MT][4];
#pragma unroll
            for (int mi = 0; mi < MT; mi++) {
                uint32_t off = (uint32_t)(warp_m0 + mi * 16 + a_row) * 128 + ks * 32 + a_sel * 16;
                uint32_t sw = SWZ128(off);
                ldsm4(ah[mi], sAh + sw);
                ldsm4(al[mi], sAl + sw);
            }
            uint32_t bh[NT][2], bl[NT][2];
#pragma unroll
            for (int j = 0; j < NT / 2; j++) {
                uint32_t off = (uint32_t)(warp_n0 + j * 16 + b_row) * 128 + ks * 32 + b_sel * 16;
                uint32_t sw = SWZ128(off);
                uint32_t t4[4];
                ldsm4(t4, sBh + sw);
                bh[2*j][0] = t4[0]; bh[2*j][1] = t4[1];
                bh[2*j+1][0] = t4[2]; bh[2*j+1][1] = t4[3];
                ldsm4(t4, sBl + sw);
                bl[2*j][0] = t4[0]; bl[2*j][1] = t4[1];
                bl[2*j+1][0] = t4[2]; bl[2*j+1][1] = t4[3];
            }
#pragma unroll
            for (int mi = 0; mi < MT; mi++)
#pragma unroll
                for (int ni = 0; ni < NT; ni++) {
                    mma_bf16(acc[mi][ni], ah[mi], bh[ni]);
                    mma_bf16(acc[mi][ni], ah[mi], bl[ni]);
                    mma_bf16(acc[mi][ni], al[mi], bh[ni]);
                }
        }
        __syncthreads();

        if (c + 2 < 16) {
            uint32_t stn = base + s * STG;
            int k0 = (c + 2) * 64;
            load_tile<128>(stn,                     Ahi, bm, k0, tid);
            load_tile<128>(stn + ATILE,             Alo, bm, k0, tid);
            load_tile<BN >(stn + 2 * ATILE,         Bhi, bn, k0, tid);
            load_tile<BN >(stn + 2 * ATILE + BTILE, Blo, bn, k0, tid);
            CP_COMMIT();
        }
    }

    // -------------------- epilogue --------------------
    const int r0base = bm + warp_m0 + (lid >> 2);
    if (ACT == 2) {
        // gates: cols 0..15 -> a, 16..31 -> b, sigmoid
#pragma unroll
        for (int ni = 0; ni < NT; ni++) {
            int col = warp_n0 + ni * 8 + (lid & 3) * 2;   // 0..31, even
            float bx = (col < 16) ? __ldg(&bias[col])      : __ldg(&bias2[col - 16]);
            float by = (col < 16) ? __ldg(&bias[col + 1])  : __ldg(&bias2[col - 15]);
            float* dst = (col < 16) ? g_a : g_bg;
            int cc = (col < 16) ? col : col - 16;
            int r0 = r0base, r1 = r0 + 8;
            float2 v0 = { sigmoidf_(acc[0][ni][0] + bx), sigmoidf_(acc[0][ni][1] + by) };
            float2 v1 = { sigmoidf_(acc[0][ni][2] + bx), sigmoidf_(acc[0][ni][3] + by) };
            *(float2*)&dst[(size_t)r0 * HH + cc] = v0;
            *(float2*)&dst[(size_t)r1 * HH + cc] = v1;
        }
    } else {
        float* __restrict__ C = (CSEL == 0) ? g_qlin : (CSEL == 1) ? g_klin
                              : (CSEL == 2) ? g_vlin : Cparam;
#pragma unroll
        for (int mi = 0; mi < MT; mi++) {
            int r0 = r0base + mi * 16, r1 = r0 + 8;
#pragma unroll
            for (int ni = 0; ni < NT; ni++) {
                int col = bn + warp_n0 + ni * 8 + (lid & 3) * 2;
                float bx = __ldg(&bias[col]), by = __ldg(&bias[col + 1]);
                float v0 = acc[mi][ni][0] + bx, v1 = acc[mi][ni][1] + by;
                float v2 = acc[mi][ni][2] + bx, v3 = acc[mi][ni][3] + by;
                if (ACT == 1) { v0 = siluf_(v0); v1 = siluf_(v1); v2 = siluf_(v2); v3 = siluf_(v3); }
                *(float2*)&C[(size_t)r0 * DIMM + col] = make_float2(v0, v1);
                *(float2*)&C[(size_t)r1 * DIMM + col] = make_float2(v2, v3);
            }
        }
    }
}

// ---------------------------------------------------------------------------
// Depthwise conv (K=4, pad=2, truncated) + SiLU + optional L2 norm
// ---------------------------------------------------------------------------
__global__ __launch_bounds__(256)
void conv_norm_kernel(const float* __restrict__ wq, const float* __restrict__ wk,
                      const float* __restrict__ wv)
{
    const int z = blockIdx.y;
    const float* __restrict__ in  = (z == 0) ? g_qlin : (z == 1) ? g_klin : g_vlin;
    const float* __restrict__ w   = (z == 0) ? wq     : (z == 1) ? wk     : wv;
    float* __restrict__ out       = (z == 0) ? g_q    : (z == 1) ? g_k    : g_v;

    const int bt = blockIdx.x;
    const int b = bt / NN;
    const int t = bt % NN;
    const int tid = threadIdx.x;
    const int c0 = tid * 4;

    float4 w0 = *(const float4*)(w + c0 * 4 + 0);
    float4 w1 = *(const float4*)(w + c0 * 4 + 4);
    float4 w2 = *(const float4*)(w + c0 * 4 + 8);
    float4 w3 = *(const float4*)(w + c0 * 4 + 12);
    float wc[4][4] = {{w0.x,w0.y,w0.z,w0.w},{w1.x,w1.y,w1.z,w1.w},
                      {w2.x,w2.y,w2.z,w2.w},{w3.x,w3.y,w3.z,w3.w}};

    float y[4] = {0.f, 0.f, 0.f, 0.f};
#pragma unroll
    for (int j = 0; j < 4; j++) {
        int tt = t + j - 2;
        if (tt >= 0 && tt < NN) {
            float4 xv = *(const float4*)(in + ((size_t)b * NN + tt) * DIMM + c0);
            y[0] += xv.x * wc[0][j];
            y[1] += xv.y * wc[1][j];
            y[2] += xv.z * wc[2][j];
            y[3] += xv.w * wc[3][j];
        }
    }
#pragma unroll
    for (int m = 0; m < 4; m++) y[m] = siluf_(y[m]);

    float ss = y[0]*y[0] + y[1]*y[1] + y[2]*y[2] + y[3]*y[3];
#pragma unroll
    for (int off = 16; off; off >>= 1) ss += __shfl_down_sync(0xffffffffu, ss, off);
    __shared__ float wss[8];
    __shared__ float inv_sh;
    const int lane = tid & 31, widx = tid >> 5;
    if (lane == 0) wss[widx] = ss;
    __syncthreads();
    if (tid == 0) {
        float tot = 0.f;
#pragma unroll
        for (int i = 0; i < 8; i++) tot += wss[i];
        inv_sh = 1.f / (sqrtf(tot) + EPSF);
    }
    __syncthreads();
    float inv = (z < 2) ? inv_sh : 1.f;

    float4 ov; ov.x = y[0]*inv; ov.y = y[1]*inv; ov.z = y[2]*inv; ov.w = y[3]*inv;
    *(float4*)(out + ((size_t)b * NN + t) * DIMM + c0) = ov;
}

// ---------------------------------------------------------------------------
// Gated delta-rule scan
// ---------------------------------------------------------------------------
__global__ __launch_bounds__(64)
void scan_kernel()
{
    const int bh = blockIdx.x;
    const int b = bh >> 4;
    const int h = bh & 15;
    const int d = threadIdx.x;

    __shared__ float k_sh[64];
    __shared__ float p_sh[64][65];

    float S[64];
#pragma unroll
    for (int e = 0; e < 64; e++) S[e] = 0.f;

    const size_t base  = ((size_t)b * NN) * DIMM + h * DHH + d;
    const size_t gbase = ((size_t)b * NN) * HH + h;

    float kd = g_k[base];
    float qd = g_q[base];
    float vd = g_v[base];
    float av = g_a[gbase];
    float bv = g_bg[gbase];

    for (int t = 0; t < NN; t++) {
        k_sh[d] = kd;
        __syncthreads();

        float kn = 0.f, qn = 0.f, vn = 0.f, an = 0.f, bn = 0.f;
        if (t + 1 < NN) {
            size_t o = base + (size_t)(t + 1) * DIMM;
            kn = g_k[o]; qn = g_q[o]; vn = g_v[o];
            size_t go = gbase + (size_t)(t + 1) * HH;
            an = g_a[go]; bn = g_bg[go];
        }

        float sk0 = 0.f, sk1 = 0.f, sk2 = 0.f, sk3 = 0.f;
#pragma unroll
        for (int e = 0; e < 64; e += 4) {
            sk0 += S[e + 0] * k_sh[e + 0];
            sk1 += S[e + 1] * k_sh[e + 1];
            sk2 += S[e + 2] * k_sh[e + 2];
            sk3 += S[e + 3] * k_sh[e + 3];
        }
        float sk = (sk0 + sk1) + (sk2 + sk3);
        float coef = bv * vd - av * bv * sk;

#pragma unroll
        for (int e = 0; e < 64; e++) {
            S[e] = av * S[e] + coef * k_sh[e];
            p_sh[e][d] = qd * S[e];
        }
        __syncthreads();

        float o0 = 0.f, o1 = 0.f, o2 = 0.f, o3 = 0.f;
#pragma unroll
        for (int r = 0; r < 64; r += 4) {
            o0 += p_sh[d][r + 0];
            o1 += p_sh[d][r + 1];
            o2 += p_sh[d][r + 2];
            o3 += p_sh[d][r + 3];
        }
        g_O[base + (size_t)t * DIMM] = (o0 + o1) + (o2 + o3);
        __syncthreads();

        kd = kn; qd = qn; vd = vn; av = an; bv = bn;
    }
}

// ---------------------------------------------------------------------------
// Launch
// ---------------------------------------------------------------------------
extern "C" void kernel_launch(void* const* d_in, const int* in_sizes, int n_in,
                              void* d_out, int out_size)
{
    (void)in_sizes; (void)n_in; (void)out_size;
    const float* x      = (const float*)d_in[0];
    const float* Wq     = (const float*)d_in[1];
    const float* bq     = (const float*)d_in[2];
    const float* Wk     = (const float*)d_in[3];
    const float* bk     = (const float*)d_in[4];
    const float* Wv     = (const float*)d_in[5];
    const float* bv     = (const float*)d_in[6];
    const float* Wa     = (const float*)d_in[7];
    const float* ba     = (const float*)d_in[8];
    const float* Wb     = (const float*)d_in[9];
    const float* bb     = (const float*)d_in[10];
    const float* conv_q = (const float*)d_in[11];
    const float* conv_k = (const float*)d_in[12];
    const float* conv_v = (const float*)d_in[13];
    const float* Wo     = (const float*)d_in[14];
    const float* bo     = (const float*)d_in[15];
    float* out = (float*)d_out;

    void *p_xhi, *p_xlo, *p_ohi, *p_olo, *p_O;
    void *p_wqh, *p_wql, *p_wkh, *p_wkl, *p_wvh, *p_wvl, *p_woh, *p_wol, *p_wabh, *p_wabl;
    cudaGetSymbolAddress(&p_xhi, g_xhi);   cudaGetSymbolAddress(&p_xlo, g_xlo);
    cudaGetSymbolAddress(&p_ohi, g_ohi);   cudaGetSymbolAddress(&p_olo, g_olo);
    cudaGetSymbolAddress(&p_O,   g_O);
    cudaGetSymbolAddress(&p_wqh, g_wq_hi); cudaGetSymbolAddress(&p_wql, g_wq_lo);
    cudaGetSymbolAddress(&p_wkh, g_wk_hi); cudaGetSymbolAddress(&p_wkl, g_wk_lo);
    cudaGetSymbolAddress(&p_wvh, g_wv_hi); cudaGetSymbolAddress(&p_wvl, g_wv_lo);
    cudaGetSymbolAddress(&p_woh, g_wo_hi); cudaGetSymbolAddress(&p_wol, g_wo_lo);
    cudaGetSymbolAddress(&p_wabh, g_wab_hi); cudaGetSymbolAddress(&p_wabl, g_wab_lo);

    const int smem_main = 1024 + 2 * (2 * 16384 + 2 * 128 * 128);  // 132096
    const int smem_gate = 1024 + 2 * (2 * 16384 + 2 * 32 * 128);   // 83968
    cudaFuncSetAttribute(hmma_gemm<128,1,0>, cudaFuncAttributeMaxDynamicSharedMemorySize, smem_main);
    cudaFuncSetAttribute(hmma_gemm<128,1,1>, cudaFuncAttributeMaxDynamicSharedMemorySize, smem_main);
    cudaFuncSetAttribute(hmma_gemm<128,1,2>, cudaFuncAttributeMaxDynamicSharedMemorySize, smem_main);
    cudaFuncSetAttribute(hmma_gemm<128,0,3>, cudaFuncAttributeMaxDynamicSharedMemorySize, smem_main);
    cudaFuncSetAttribute(hmma_gemm<32,2,4>,  cudaFuncAttributeMaxDynamicSharedMemorySize, smem_gate);

    // conversions
    cvt_pair_kernel<<<16384, 256>>>(x,  (__nv_bfloat16*)p_xhi, (__nv_bfloat16*)p_xlo, MM*DIMM/4);
    cvt_pair_kernel<<<1024, 256>>>(Wq, (__nv_bfloat16*)p_wqh, (__nv_bfloat16*)p_wql, DIMM*DIMM/4);
    cvt_pair_kernel<<<1024, 256>>>(Wk, (__nv_bfloat16*)p_wkh, (__nv_bfloat16*)p_wkl, DIMM*DIMM/4);
    cvt_pair_kernel<<<1024, 256>>>(Wv, (__nv_bfloat16*)p_wvh, (__nv_bfloat16*)p_wvl, DIMM*DIMM/4);
    cvt_pair_kernel<<<1024, 256>>>(Wo, (__nv_bfloat16*)p_woh, (__nv_bfloat16*)p_wol, DIMM*DIMM/4);
    cvt_pair_kernel<<<16, 256>>>(Wa, (__nv_bfloat16*)p_wabh, (__nv_bfloat16*)p_wabl, HH*DIMM/4);
    cvt_pair_kernel<<<16, 256>>>(Wb, ((__nv_bfloat16*)p_wabh) + HH*DIMM,
                                 ((__nv_bfloat16*)p_wabl) + HH*DIMM, HH*DIMM/4);

    dim3 gmain(8, 128);
    hmma_gemm<128,1,0><<<gmain, 256, smem_main>>>((const __nv_bfloat16*)p_xhi, (const __nv_bfloat16*)p_xlo,
                                                  (const __nv_bfloat16*)p_wqh, (const __nv_bfloat16*)p_wql,
                                                  bq, nullptr, nullptr);
    hmma_gemm<128,1,1><<<gmain, 256, smem_main>>>((const __nv_bfloat16*)p_xhi, (const __nv_bfloat16*)p_xlo,
                                                  (const __nv_bfloat16*)p_wkh, (const __nv_bfloat16*)p_wkl,
                                                  bk, nullptr, nullptr);
    hmma_gemm<128,1,2><<<gmain, 256, smem_main>>>((const __nv_bfloat16*)p_xhi, (const __nv_bfloat16*)p_xlo,
                                                  (const __nv_bfloat16*)p_wvh, (const __nv_bfloat16*)p_wvl,
                                                  bv, nullptr, nullptr);
    hmma_gemm<32,2,4><<<dim3(1,128), 256, smem_gate>>>((const __nv_bfloat16*)p_xhi, (const __nv_bfloat16*)p_xlo,
                                                  (const __nv_bfloat16*)p_wabh, (const __nv_bfloat16*)p_wabl,
                                                  ba, bb, nullptr);

    conv_norm_kernel<<<dim3(MM, 3), 256>>>(conv_q, conv_k, conv_v);

    scan_kernel<<<BB * HH, 64>>>();

    cvt_pair_kernel<<<16384, 256>>>((const float*)p_O, (__nv_bfloat16*)p_ohi, (__nv_bfloat16*)p_olo, MM*DIMM/4);

    hmma_gemm<128,0,3><<<gmain, 256, smem_main>>>((const __nv_bfloat16*)p_ohi, (const __nv_bfloat16*)p_olo,
                                                  (const __nv_bfloat16*)p_woh, (const __nv_bfloat16*)p_wol,
                                                  bo, nullptr, out);
}

// round 5
// speedup vs baseline: 1.8371x; 1.0736x over previous
#include <cuda_runtime.h>
#include <cuda_bf16.h>
#include <cstdint>

// Problem constants
#define BB   8
#define NN   2048
#define DIMM 1024
#define HH   16
#define DHH  64
#define MM   (BB*NN)          // 16384 rows
#define EPSF 1e-6f

// ---------------------------------------------------------------------------
// Scratch (device globals; no allocation allowed)
// ---------------------------------------------------------------------------
__device__ float g_qlin[BB*NN*DIMM];
__device__ float g_klin[BB*NN*DIMM];
__device__ float g_vlin[BB*NN*DIMM];
__device__ float g_q[BB*NN*DIMM];
__device__ float g_k[BB*NN*DIMM];
__device__ float g_v[BB*NN*DIMM];
__device__ float g_a[BB*NN*HH];
__device__ float g_bg[BB*NN*HH];

__device__ __nv_bfloat16 g_xhi[BB*NN*DIMM];
__device__ __nv_bfloat16 g_xlo[BB*NN*DIMM];
__device__ __nv_bfloat16 g_ohi[BB*NN*DIMM];
__device__ __nv_bfloat16 g_olo[BB*NN*DIMM];
__device__ __nv_bfloat16 g_wq_hi[DIMM*DIMM];
__device__ __nv_bfloat16 g_wq_lo[DIMM*DIMM];
__device__ __nv_bfloat16 g_wk_hi[DIMM*DIMM];
__device__ __nv_bfloat16 g_wk_lo[DIMM*DIMM];
__device__ __nv_bfloat16 g_wv_hi[DIMM*DIMM];
__device__ __nv_bfloat16 g_wv_lo[DIMM*DIMM];
__device__ __nv_bfloat16 g_wo_hi[DIMM*DIMM];
__device__ __nv_bfloat16 g_wo_lo[DIMM*DIMM];
__device__ __nv_bfloat16 g_wab_hi[32*DIMM];
__device__ __nv_bfloat16 g_wab_lo[32*DIMM];

__device__ __forceinline__ float sigmoidf_(float x) { return 1.f / (1.f + __expf(-x)); }
__device__ __forceinline__ float siluf_(float x)    { return x / (1.f + __expf(-x)); }

// ---------------------------------------------------------------------------
// PTX helpers
// ---------------------------------------------------------------------------
__device__ __forceinline__ uint32_t smem_u32(const void* p) {
    uint32_t a;
    asm("{ .reg .u64 t; cvta.to.shared.u64 t, %1; cvt.u32.u64 %0, t; }" : "=r"(a) : "l"(p));
    return a;
}
#define SWZ128(o) ((o) ^ (((o) >> 3) & 0x70))

__device__ __forceinline__ void cp_async16(uint32_t dst, const void* src) {
    asm volatile("cp.async.ca.shared.global [%0], [%1], 16;\n" :: "r"(dst), "l"(src));
}
#define CP_COMMIT() asm volatile("cp.async.commit_group;\n" ::: "memory")
#define CP_WAIT1()  asm volatile("cp.async.wait_group 1;\n" ::: "memory")
#define CP_WAIT0()  asm volatile("cp.async.wait_group 0;\n" ::: "memory")

__device__ __forceinline__ void ldsm4(uint32_t* r, uint32_t addr) {
    asm volatile("ldmatrix.sync.aligned.m8n8.x4.shared.b16 {%0,%1,%2,%3}, [%4];"
                 : "=r"(r[0]), "=r"(r[1]), "=r"(r[2]), "=r"(r[3]) : "r"(addr));
}
__device__ __forceinline__ void mma_bf16(float* d, const uint32_t* a, const uint32_t* b) {
    asm volatile(
        "mma.sync.aligned.m16n8k16.row.col.f32.bf16.bf16.f32 "
        "{%0,%1,%2,%3}, {%4,%5,%6,%7}, {%8,%9}, {%0,%1,%2,%3};"
        : "+f"(d[0]), "+f"(d[1]), "+f"(d[2]), "+f"(d[3])
        : "r"(a[0]), "r"(a[1]), "r"(a[2]), "r"(a[3]), "r"(b[0]), "r"(b[1]));
}

// ---------------------------------------------------------------------------
// Split conversions
// ---------------------------------------------------------------------------
__device__ __forceinline__ void split4(const float4 v, uint2& hv, uint2& lv) {
    __nv_bfloat16 h0 = __float2bfloat16(v.x), h1 = __float2bfloat16(v.y);
    __nv_bfloat16 h2 = __float2bfloat16(v.z), h3 = __float2bfloat16(v.w);
    __nv_bfloat16 l0 = __float2bfloat16(v.x - __bfloat162float(h0));
    __nv_bfloat16 l1 = __float2bfloat16(v.y - __bfloat162float(h1));
    __nv_bfloat16 l2 = __float2bfloat16(v.z - __bfloat162float(h2));
    __nv_bfloat16 l3 = __float2bfloat16(v.w - __bfloat162float(h3));
    hv.x = (uint32_t)__bfloat16_as_ushort(h0) | ((uint32_t)__bfloat16_as_ushort(h1) << 16);
    hv.y = (uint32_t)__bfloat16_as_ushort(h2) | ((uint32_t)__bfloat16_as_ushort(h3) << 16);
    lv.x = (uint32_t)__bfloat16_as_ushort(l0) | ((uint32_t)__bfloat16_as_ushort(l1) << 16);
    lv.y = (uint32_t)__bfloat16_as_ushort(l2) | ((uint32_t)__bfloat16_as_ushort(l3) << 16);
}

__global__ __launch_bounds__(256)
void cvt_pair_kernel(const float* __restrict__ src, __nv_bfloat16* __restrict__ hi,
                     __nv_bfloat16* __restrict__ lo, int n4)
{
    int i = blockIdx.x * blockDim.x + threadIdx.x;
    if (i >= n4) return;
    uint2 hv, lv;
    split4(((const float4*)src)[i], hv, lv);
    ((uint2*)hi)[i] = hv;
    ((uint2*)lo)[i] = lv;
}

// merged big-weight conversion: z = 0..3 -> Wq,Wk,Wv,Wo
__global__ __launch_bounds__(256)
void cvt_w_kernel(const float* __restrict__ Wq, const float* __restrict__ Wk,
                  const float* __restrict__ Wv, const float* __restrict__ Wo)
{
    const int z = blockIdx.y;
    const float* src = (z == 0) ? Wq : (z == 1) ? Wk : (z == 2) ? Wv : Wo;
    __nv_bfloat16* hi = (z == 0) ? g_wq_hi : (z == 1) ? g_wk_hi : (z == 2) ? g_wv_hi : g_wo_hi;
    __nv_bfloat16* lo = (z == 0) ? g_wq_lo : (z == 1) ? g_wk_lo : (z == 2) ? g_wv_lo : g_wo_lo;
    int i = blockIdx.x * blockDim.x + threadIdx.x;
    uint2 hv, lv;
    split4(((const float4*)src)[i], hv, lv);
    ((uint2*)hi)[i] = hv;
    ((uint2*)lo)[i] = lv;
}

// gate-weight conversion into concat buffer: z=0 -> Wa rows 0..15, z=1 -> Wb rows 16..31
__global__ __launch_bounds__(256)
void cvt_ab_kernel(const float* __restrict__ Wa, const float* __restrict__ Wb)
{
    const int z = blockIdx.y;
    const float* src = z ? Wb : Wa;
    const int off4 = z ? (HH * DIMM / 4) : 0;
    int i = blockIdx.x * blockDim.x + threadIdx.x;
    uint2 hv, lv;
    split4(((const float4*)src)[i], hv, lv);
    ((uint2*)g_wab_hi)[off4 + i] = hv;
    ((uint2*)g_wab_lo)[off4 + i] = lv;
}

// ---------------------------------------------------------------------------
// Big HMMA GEMM: CTA tile 256x128, warp tile 64x64 (4 m-warps x 2 n-warps),
// K chunk 64, 2-stage cp.async pipeline, bf16 3-pass split.
// MODE 0: QKV merged (wsel = blockIdx.x>>3), SiLU epilogue -> g_{q,k,v}lin.
// MODE 1: O GEMM, no act, -> Cout.
// ---------------------------------------------------------------------------
template<int ROWS>
__device__ __forceinline__ void load_tile(uint32_t dst, const __nv_bfloat16* __restrict__ g,
                                          int row0, int k0, int tid)
{
    constexpr int ITERS = ROWS * 8 / 256;
#pragma unroll
    for (int i = 0; i < ITERS; i++) {
        int sidx = tid + i * 256;
        int r = sidx >> 3, s = sidx & 7;
        cp_async16(dst + SWZ128(r * 128 + s * 16),
                   g + ((size_t)(row0 + r) * DIMM + k0 + s * 8));
    }
}

template<int MODE>
__global__ __launch_bounds__(256, 1)
void hmma_big(const float* __restrict__ bias_q, const float* __restrict__ bias_k,
              const float* __restrict__ bias_v, float* __restrict__ Cout)
{
    extern __shared__ char smraw[];
    uint32_t base = (smem_u32(smraw) + 1023u) & ~1023u;

    constexpr int ATILE = 256 * 128;   // bytes per A operand tile
    constexpr int BTILE = 128 * 128;
    constexpr int STG   = 2 * ATILE + 2 * BTILE;   // 96KB

    const __nv_bfloat16 *Ahi, *Alo, *Bhi, *Blo;
    const float* bias;
    float* C;
    int bn_idx;
    if (MODE == 0) {
        const int wsel = blockIdx.x >> 3;
        bn_idx = blockIdx.x & 7;
        Ahi = g_xhi; Alo = g_xlo;
        Bhi  = (wsel == 0) ? g_wq_hi : (wsel == 1) ? g_wk_hi : g_wv_hi;
        Blo  = (wsel == 0) ? g_wq_lo : (wsel == 1) ? g_wk_lo : g_wv_lo;
        bias = (wsel == 0) ? bias_q  : (wsel == 1) ? bias_k  : bias_v;
        C    = (wsel == 0) ? g_qlin  : (wsel == 1) ? g_klin  : g_vlin;
    } else {
        bn_idx = blockIdx.x;
        Ahi = g_ohi; Alo = g_olo; Bhi = g_wo_hi; Blo = g_wo_lo;
        bias = bias_q; C = Cout;
    }

    const int tid = threadIdx.x;
    const int wid = tid >> 5;
    const int lid = tid & 31;
    const int bm = blockIdx.y * 256;
    const int bn = bn_idx * 128;

    const int warp_m0 = (wid & 3) * 64;
    const int warp_n0 = (wid >> 2) * 64;

    const int a_row = lid & 15;
    const int a_sel = lid >> 4;
    const int b_row = (lid & 7) + ((lid >> 4) << 3);
    const int b_sel = (lid >> 3) & 1;

    // prologue: chunk 0 -> stage 0, chunk 1 -> stage 1
#pragma unroll
    for (int c = 0; c < 2; c++) {
        uint32_t st = base + c * STG;
        int k0 = c * 64;
        load_tile<256>(st,                     Ahi, bm, k0, tid);
        load_tile<256>(st + ATILE,             Alo, bm, k0, tid);
        load_tile<128>(st + 2 * ATILE,         Bhi, bn, k0, tid);
        load_tile<128>(st + 2 * ATILE + BTILE, Blo, bn, k0, tid);
        CP_COMMIT();
    }

    float acc[4][8][4];
#pragma unroll
    for (int mi = 0; mi < 4; mi++)
#pragma unroll
        for (int ni = 0; ni < 8; ni++)
#pragma unroll
            for (int j = 0; j < 4; j++) acc[mi][ni][j] = 0.f;

    for (int c = 0; c < 16; c++) {
        const int s = c & 1;
        const uint32_t st = base + s * STG;
        if (c == 15) CP_WAIT0(); else CP_WAIT1();
        __syncthreads();

        const uint32_t sAh = st, sAl = st + ATILE;
        const uint32_t sBh = st + 2 * ATILE, sBl = st + 2 * ATILE + BTILE;

#pragma unroll
        for (int ks = 0; ks < 4; ks++) {
            uint32_t bh[8][2], bl[8][2];
#pragma unroll
            for (int j = 0; j < 4; j++) {
                uint32_t off = (uint32_t)(warp_n0 + j * 16 + b_row) * 128 + ks * 32 + b_sel * 16;
                uint32_t sw = SWZ128(off);
                uint32_t t4[4];
                ldsm4(t4, sBh + sw);
                bh[2*j][0] = t4[0]; bh[2*j][1] = t4[1];
                bh[2*j+1][0] = t4[2]; bh[2*j+1][1] = t4[3];
                ldsm4(t4, sBl + sw);
                bl[2*j][0] = t4[0]; bl[2*j][1] = t4[1];
                bl[2*j+1][0] = t4[2]; bl[2*j+1][1] = t4[3];
            }
#pragma unroll
            for (int mi = 0; mi < 4; mi++) {
                uint32_t ah[4], al[4];
                uint32_t off = (uint32_t)(warp_m0 + mi * 16 + a_row) * 128 + ks * 32 + a_sel * 16;
                uint32_t sw = SWZ128(off);
                ldsm4(ah, sAh + sw);
                ldsm4(al, sAl + sw);
#pragma unroll
                for (int ni = 0; ni < 8; ni++) {
                    mma_bf16(acc[mi][ni], ah, bh[ni]);
                    mma_bf16(acc[mi][ni], ah, bl[ni]);
                    mma_bf16(acc[mi][ni], al, bh[ni]);
                }
            }
        }
        __syncthreads();

        if (c + 2 < 16) {
            uint32_t stn = base + s * STG;
            int k0 = (c + 2) * 64;
            load_tile<256>(stn,                     Ahi, bm, k0, tid);
            load_tile<256>(stn + ATILE,             Alo, bm, k0, tid);
            load_tile<128>(stn + 2 * ATILE,         Bhi, bn, k0, tid);
            load_tile<128>(stn + 2 * ATILE + BTILE, Blo, bn, k0, tid);
            CP_COMMIT();
        }
    }

    // epilogue
#pragma unroll
    for (int mi = 0; mi < 4; mi++) {
        int r0 = bm + warp_m0 + mi * 16 + (lid >> 2);
        int r1 = r0 + 8;
#pragma unroll
        for (int ni = 0; ni < 8; ni++) {
            int col = bn + warp_n0 + ni * 8 + (lid & 3) * 2;
            float bx = __ldg(&bias[col]), by = __ldg(&bias[col + 1]);
            float v0 = acc[mi][ni][0] + bx, v1 = acc[mi][ni][1] + by;
            float v2 = acc[mi][ni][2] + bx, v3 = acc[mi][ni][3] + by;
            if (MODE == 0) { v0 = siluf_(v0); v1 = siluf_(v1); v2 = siluf_(v2); v3 = siluf_(v3); }
            *(float2*)&C[(size_t)r0 * DIMM + col] = make_float2(v0, v1);
            *(float2*)&C[(size_t)r1 * DIMM + col] = make_float2(v2, v3);
        }
    }
}

// ---------------------------------------------------------------------------
// Gate GEMM (BN=32): sigmoid(x@Wab^T + b) -> g_a / g_bg  (proven round-3 path)
// ---------------------------------------------------------------------------
__global__ __launch_bounds__(256, 1)
void hmma_gate(const float* __restrict__ ba, const float* __restrict__ bb)
{
    extern __shared__ char smraw[];
    uint32_t base = (smem_u32(smraw) + 1023u) & ~1023u;

    constexpr int ATILE = 128 * 128;
    constexpr int BTILE = 32 * 128;
    constexpr int STG   = 2 * ATILE + 2 * BTILE;

    const int tid = threadIdx.x;
    const int wid = tid >> 5;
    const int lid = tid & 31;
    const int bm = blockIdx.y * 128;

    const int warp_m0 = wid * 16;   // 8 m-warps, warp tile 16x32
    const int a_row = lid & 15;
    const int a_sel = lid >> 4;
    const int b_row = (lid & 7) + ((lid >> 4) << 3);
    const int b_sel = (lid >> 3) & 1;

#pragma unroll
    for (int c = 0; c < 2; c++) {
        uint32_t st = base + c * STG;
        int k0 = c * 64;
        load_tile<128>(st,                     g_xhi,   bm, k0, tid);
        load_tile<128>(st + ATILE,             g_xlo,   bm, k0, tid);
        load_tile<32 >(st + 2 * ATILE,         g_wab_hi, 0, k0, tid);
        load_tile<32 >(st + 2 * ATILE + BTILE, g_wab_lo, 0, k0, tid);
        CP_COMMIT();
    }

    float acc[4][4];
#pragma unroll
    for (int ni = 0; ni < 4; ni++)
#pragma unroll
        for (int j = 0; j < 4; j++) acc[ni][j] = 0.f;

    for (int c = 0; c < 16; c++) {
        const int s = c & 1;
        const uint32_t st = base + s * STG;
        if (c == 15) CP_WAIT0(); else CP_WAIT1();
        __syncthreads();

        const uint32_t sAh = st, sAl = st + ATILE;
        const uint32_t sBh = st + 2 * ATILE, sBl = st + 2 * ATILE + BTILE;

#pragma unroll
        for (int ks = 0; ks < 4; ks++) {
            uint32_t ah[4], al[4];
            {
                uint32_t off = (uint32_t)(warp_m0 + a_row) * 128 + ks * 32 + a_sel * 16;
                uint32_t sw = SWZ128(off);
                ldsm4(ah, sAh + sw);
                ldsm4(al, sAl + sw);
            }
            uint32_t bh[4][2], bl[4][2];
#pragma unroll
            for (int j = 0; j < 2; j++) {
                uint32_t off = (uint32_t)(j * 16 + b_row) * 128 + ks * 32 + b_sel * 16;
                uint32_t sw = SWZ128(off);
                uint32_t t4[4];
                ldsm4(t4, sBh + sw);
                bh[2*j][0] = t4[0]; bh[2*j][1] = t4[1];
                bh[2*j+1][0] = t4[2]; bh[2*j+1][1] = t4[3];
                ldsm4(t4, sBl + sw);
                bl[2*j][0] = t4[0]; bl[2*j][1] = t4[1];
                bl[2*j+1][0] = t4[2]; bl[2*j+1][1] = t4[3];
            }
#pragma unroll
            for (int ni = 0; ni < 4; ni++) {
                mma_bf16(acc[ni], ah, bh[ni]);
                mma_bf16(acc[ni], ah, bl[ni]);
                mma_bf16(acc[ni], al, bh[ni]);
            }
        }
        __syncthreads();

        if (c + 2 < 16) {
            uint32_t stn = base + s * STG;
            int k0 = (c + 2) * 64;
            load_tile<128>(stn,                     g_xhi,   bm, k0, tid);
            load_tile<128>(stn + ATILE,             g_xlo,   bm, k0, tid);
            load_tile<32 >(stn + 2 * ATILE,         g_wab_hi, 0, k0, tid);
            load_tile<32 >(stn + 2 * ATILE + BTILE, g_wab_lo, 0, k0, tid);
            CP_COMMIT();
        }
    }

    const int r0 = bm + warp_m0 + (lid >> 2);
#pragma unroll
    for (int ni = 0; ni < 4; ni++) {
        int col = ni * 8 + (lid & 3) * 2;   // 0..31, even
        float bx = (col < 16) ? __ldg(&ba[col])     : __ldg(&bb[col - 16]);
        float by = (col < 16) ? __ldg(&ba[col + 1]) : __ldg(&bb[col - 15]);
        float* dst = (col < 16) ? g_a : g_bg;
        int cc = (col < 16) ? col : col - 16;
        float2 v0 = { sigmoidf_(acc[ni][0] + bx), sigmoidf_(acc[ni][1] + by) };
        float2 v1 = { sigmoidf_(acc[ni][2] + bx), sigmoidf_(acc[ni][3] + by) };
        *(float2*)&dst[(size_t)r0 * HH + cc] = v0;
        *(float2*)&dst[(size_t)(r0 + 8) * HH + cc] = v1;
    }
}

// ---------------------------------------------------------------------------
// Depthwise conv (K=4, pad=2, truncated) + SiLU + optional L2 norm
// ---------------------------------------------------------------------------
__global__ __launch_bounds__(256)
void conv_norm_kernel(const float* __restrict__ wq, const float* __restrict__ wk,
                      const float* __restrict__ wv)
{
    const int z = blockIdx.y;
    const float* __restrict__ in  = (z == 0) ? g_qlin : (z == 1) ? g_klin : g_vlin;
    const float* __restrict__ w   = (z == 0) ? wq     : (z == 1) ? wk     : wv;
    float* __restrict__ out       = (z == 0) ? g_q    : (z == 1) ? g_k    : g_v;

    const int bt = blockIdx.x;
    const int b = bt / NN;
    const int t = bt % NN;
    const int tid = threadIdx.x;
    const int c0 = tid * 4;

    float4 w0 = *(const float4*)(w + c0 * 4 + 0);
    float4 w1 = *(const float4*)(w + c0 * 4 + 4);
    float4 w2 = *(const float4*)(w + c0 * 4 + 8);
    float4 w3 = *(const float4*)(w + c0 * 4 + 12);
    float wc[4][4] = {{w0.x,w0.y,w0.z,w0.w},{w1.x,w1.y,w1.z,w1.w},
                      {w2.x,w2.y,w2.z,w2.w},{w3.x,w3.y,w3.z,w3.w}};

    float y[4] = {0.f, 0.f, 0.f, 0.f};
#pragma unroll
    for (int j = 0; j < 4; j++) {
        int tt = t + j - 2;
        if (tt >= 0 && tt < NN) {
            float4 xv = *(const float4*)(in + ((size_t)b * NN + tt) * DIMM + c0);
            y[0] += xv.x * wc[0][j];
            y[1] += xv.y * wc[1][j];
            y[2] += xv.z * wc[2][j];
            y[3] += xv.w * wc[3][j];
        }
    }
#pragma unroll
    for (int m = 0; m < 4; m++) y[m] = siluf_(y[m]);

    float ss = y[0]*y[0] + y[1]*y[1] + y[2]*y[2] + y[3]*y[3];
#pragma unroll
    for (int off = 16; off; off >>= 1) ss += __shfl_down_sync(0xffffffffu, ss, off);
    __shared__ float wss[8];
    __shared__ float inv_sh;
    const int lane = tid & 31, widx = tid >> 5;
    if (lane == 0) wss[widx] = ss;
    __syncthreads();
    if (tid == 0) {
        float tot = 0.f;
#pragma unroll
        for (int i = 0; i < 8; i++) tot += wss[i];
        inv_sh = 1.f / (sqrtf(tot) + EPSF);
    }
    __syncthreads();
    float inv = (z < 2) ? inv_sh : 1.f;

    float4 ov; ov.x = y[0]*inv; ov.y = y[1]*inv; ov.z = y[2]*inv; ov.w = y[3]*inv;
    *(float4*)(out + ((size_t)b * NN + t) * DIMM + c0) = ov;
}

// ---------------------------------------------------------------------------
// Gated delta-rule scan, dual-state (S + S^T), 128 threads per (b,h).
// Threads 0..63  : own S row d   -> Sk dot, coef, S update.
// Threads 64..127: own S^T row e -> T update + o_e = sum_d T[e][d]*q[d] (local),
//                  writes O directly as bf16 hi/lo split.
// Double-buffered k/q in smem; 2 barriers per step.
// ---------------------------------------------------------------------------
__global__ __launch_bounds__(128)
void scan_kernel()
{
    const int bh = blockIdx.x;
    const int b = bh >> 4;
    const int h = bh & 15;
    const int tid = threadIdx.x;

    __shared__ __align__(16) float k_sh[2][64];
    __shared__ __align__(16) float q_sh[2][64];
    __shared__ __align__(16) float coef_sh[64];

    const size_t gb = ((size_t)b * NN) * HH + h;

    if (tid < 64) {
        // ---- group 0: S rows ----
        const int d = tid;
        const size_t base = ((size_t)b * NN) * DIMM + h * DHH + d;
        float S[64];
#pragma unroll
        for (int e = 0; e < 64; e++) S[e] = 0.f;
        float vc = g_v[base], ac = g_a[gb], bc = g_bg[gb];
        __syncthreads();   // init: k_sh[0], q_sh[0] ready

        for (int t = 0; t < NN; t++) {
            const float4* kb = (const float4*)k_sh[t & 1];
            float sk0 = 0.f, sk1 = 0.f, sk2 = 0.f, sk3 = 0.f;
#pragma unroll
            for (int i = 0; i < 16; i++) {
                float4 kv = kb[i];
                sk0 += S[4*i+0] * kv.x; sk1 += S[4*i+1] * kv.y;
                sk2 += S[4*i+2] * kv.z; sk3 += S[4*i+3] * kv.w;
            }
            float coef = bc * vc - ac * bc * ((sk0 + sk1) + (sk2 + sk3));
            coef_sh[d] = coef;
            float vn = 0.f, an = 0.f, bn = 0.f;
            if (t + 1 < NN) {
                vn = g_v[base + (size_t)(t + 1) * DIMM];
                an = g_a[gb + (size_t)(t + 1) * HH];
                bn = g_bg[gb + (size_t)(t + 1) * HH];
            }
            __syncthreads();   // bar A: coef visible to g1
            float av = ac;
#pragma unroll
            for (int i = 0; i < 16; i++) {
                float4 kv = kb[i];
                S[4*i+0] = av * S[4*i+0] + coef * kv.x;
                S[4*i+1] = av * S[4*i+1] + coef * kv.y;
                S[4*i+2] = av * S[4*i+2] + coef * kv.z;
                S[4*i+3] = av * S[4*i+3] + coef * kv.w;
            }
            vc = vn; ac = an; bc = bn;
            __syncthreads();   // bar B: next k/q buffer committed by g1
        }
    } else {
        // ---- group 1: S^T rows ----
        const int e = tid - 64;
        const size_t base = ((size_t)b * NN) * DIMM + h * DHH + e;
        float T[64];
#pragma unroll
        for (int d = 0; d < 64; d++) T[d] = 0.f;
        float kc = g_k[base];
        float qc = g_q[base];
        k_sh[0][e] = kc;
        q_sh[0][e] = qc;
        float ac = g_a[gb];
        float kn = 0.f, qn = 0.f;
        if (NN > 1) { kn = g_k[base + DIMM]; qn = g_q[base + DIMM]; }
        __syncthreads();   // init

        for (int t = 0; t < NN; t++) {
            const int buf = t & 1;
            float an = 0.f, kn2 = 0.f, qn2 = 0.f;
            if (t + 1 < NN) an = g_a[gb + (size_t)(t + 1) * HH];
            if (t + 2 < NN) {
                kn2 = g_k[base + (size_t)(t + 2) * DIMM];
                qn2 = g_q[base + (size_t)(t + 2) * DIMM];
            }
            __syncthreads();   // bar A: coef ready
            const float av = ac;
            const float4* cf4 = (const float4*)coef_sh;
            const float4* qb  = (const float4*)q_sh[buf];
            float o0 = 0.f, o1 = 0.f, o2 = 0.f, o3 = 0.f;
#pragma unroll
            for (int i = 0; i < 16; i++) {
                float4 cf = cf4[i];
                float4 qv = qb[i];
                float t0 = av * T[4*i+0] + cf.x * kc; T[4*i+0] = t0; o0 += t0 * qv.x;
                float t1 = av * T[4*i+1] + cf.y * kc; T[4*i+1] = t1; o1 += t1 * qv.y;
                float t2 = av * T[4*i+2] + cf.z * kc; T[4*i+2] = t2; o2 += t2 * qv.z;
                float t3 = av * T[4*i+3] + cf.w * kc; T[4*i+3] = t3; o3 += t3 * qv.w;
            }
            float o = (o0 + o1) + (o2 + o3);
            __nv_bfloat16 hi = __float2bfloat16(o);
            __nv_bfloat16 lo = __float2bfloat16(o - __bfloat162float(hi));
            g_ohi[base + (size_t)t * DIMM] = hi;
            g_olo[base + (size_t)t * DIMM] = lo;
            if (t + 1 < NN) {
                k_sh[buf ^ 1][e] = kn;
                q_sh[buf ^ 1][e] = qn;
            }
            kc = kn; kn = kn2; qn = qn2; ac = an;
            __syncthreads();   // bar B
        }
    }
}

// ---------------------------------------------------------------------------
// Launch
// ---------------------------------------------------------------------------
extern "C" void kernel_launch(void* const* d_in, const int* in_sizes, int n_in,
                              void* d_out, int out_size)
{
    (void)in_sizes; (void)n_in; (void)out_size;
    const float* x      = (const float*)d_in[0];
    const float* Wq     = (const float*)d_in[1];
    const float* bq     = (const float*)d_in[2];
    const float* Wk     = (const float*)d_in[3];
    const float* bk     = (const float*)d_in[4];
    const float* Wv     = (const float*)d_in[5];
    const float* bv     = (const float*)d_in[6];
    const float* Wa     = (const float*)d_in[7];
    const float* ba     = (const float*)d_in[8];
    const float* Wb     = (const float*)d_in[9];
    const float* bb     = (const float*)d_in[10];
    const float* conv_q = (const float*)d_in[11];
    const float* conv_k = (const float*)d_in[12];
    const float* conv_v = (const float*)d_in[13];
    const float* Wo     = (const float*)d_in[14];
    const float* bo     = (const float*)d_in[15];
    float* out = (float*)d_out;

    void *p_xhi, *p_xlo;
    cudaGetSymbolAddress(&p_xhi, g_xhi);
    cudaGetSymbolAddress(&p_xlo, g_xlo);

    const int smem_big  = 1024 + 2 * (2 * 256 * 128 + 2 * 128 * 128);  // 197632
    const int smem_gate = 1024 + 2 * (2 * 128 * 128 + 2 * 32 * 128);   // 74752
    cudaFuncSetAttribute(hmma_big<0>, cudaFuncAttributeMaxDynamicSharedMemorySize, smem_big);
    cudaFuncSetAttribute(hmma_big<1>, cudaFuncAttributeMaxDynamicSharedMemorySize, smem_big);
    cudaFuncSetAttribute(hmma_gate,   cudaFuncAttributeMaxDynamicSharedMemorySize, smem_gate);

    const int half4 = MM * DIMM / 8;           // float4 groups per half of x
    // [0],[1]: x conversion in two halves
    cvt_pair_kernel<<<half4 / 256, 256>>>(x, (__nv_bfloat16*)p_xhi, (__nv_bfloat16*)p_xlo, half4);
    cvt_pair_kernel<<<half4 / 256, 256>>>(x + (size_t)MM * DIMM / 2,
                                          (__nv_bfloat16*)p_xhi + (size_t)MM * DIMM / 2,
                                          (__nv_bfloat16*)p_xlo + (size_t)MM * DIMM / 2, half4);
    // [2]: big weights, [3]: gate weights
    cvt_w_kernel<<<dim3(DIMM * DIMM / 4 / 256, 4), 256>>>(Wq, Wk, Wv, Wo);
    cvt_ab_kernel<<<dim3(HH * DIMM / 4 / 256, 2), 256>>>(Wa, Wb);
    // [4]: gates
    hmma_gate<<<dim3(1, 128), 256, smem_gate>>>(ba, bb);
    // [5]: merged QKV GEMM (ncu -s 5 captures this)
    hmma_big<0><<<dim3(24, 64), 256, smem_big>>>(bq, bk, bv, nullptr);
    // [6]: conv + norm
    conv_norm_kernel<<<dim3(MM, 3), 256>>>(conv_q, conv_k, conv_v);
    // [7]: scan (writes O as bf16 hi/lo directly)
    scan_kernel<<<BB * HH, 128>>>();
    // [8]: output projection
    hmma_big<1><<<dim3(8, 64), 256, smem_big>>>(bo, nullptr, nullptr, out);
}

// round 6
// speedup vs baseline: 2.0939x; 1.1398x over previous
#include <cuda_runtime.h>
#include <cuda_bf16.h>
#include <cstdint>

// Problem constants
#define BB   8
#define NN   2048
#define DIMM 1024
#define HH   16
#define DHH  64
#define MM   (BB*NN)          // 16384 rows
#define EPSF 1e-6f

// ---------------------------------------------------------------------------
// Scratch (device globals; no allocation allowed)
// ---------------------------------------------------------------------------
__device__ float g_qlin[BB*NN*DIMM];
__device__ float g_klin[BB*NN*DIMM];
__device__ float g_vlin[BB*NN*DIMM];
__device__ float g_q[BB*NN*DIMM];
__device__ float g_k[BB*NN*DIMM];
__device__ float g_v[BB*NN*DIMM];
__device__ float g_a[BB*NN*HH];
__device__ float g_bg[BB*NN*HH];

// chunk-packed, pre-swizzled bf16 operands: layout [c][row][128B], where the
// 128B row already carries the SW128 xor  (ib ^ ((row&7)<<4)).
__device__ __nv_bfloat16 g_xhi[MM*DIMM];
__device__ __nv_bfloat16 g_xlo[MM*DIMM];
__device__ __nv_bfloat16 g_ohi[MM*DIMM];
__device__ __nv_bfloat16 g_olo[MM*DIMM];
__device__ __nv_bfloat16 g_wq_hi[DIMM*DIMM];
__device__ __nv_bfloat16 g_wq_lo[DIMM*DIMM];
__device__ __nv_bfloat16 g_wk_hi[DIMM*DIMM];
__device__ __nv_bfloat16 g_wk_lo[DIMM*DIMM];
__device__ __nv_bfloat16 g_wv_hi[DIMM*DIMM];
__device__ __nv_bfloat16 g_wv_lo[DIMM*DIMM];
__device__ __nv_bfloat16 g_wo_hi[DIMM*DIMM];
__device__ __nv_bfloat16 g_wo_lo[DIMM*DIMM];
__device__ __nv_bfloat16 g_wab_hi[32*DIMM];
__device__ __nv_bfloat16 g_wab_lo[32*DIMM];

__device__ __forceinline__ float sigmoidf_(float x) { return 1.f / (1.f + __expf(-x)); }
__device__ __forceinline__ float siluf_(float x)    { return x / (1.f + __expf(-x)); }

// ---------------------------------------------------------------------------
// PTX helpers
// ---------------------------------------------------------------------------
__device__ __forceinline__ uint32_t smem_u32(const void* p) {
    uint32_t a;
    asm("{ .reg .u64 t; cvta.to.shared.u64 t, %1; cvt.u32.u64 %0, t; }" : "=r"(a) : "l"(p));
    return a;
}
#define SWZ128(o) ((o) ^ (((o) >> 3) & 0x70))

__device__ __forceinline__ void ldsm4(uint32_t* r, uint32_t addr) {
    asm volatile("ldmatrix.sync.aligned.m8n8.x4.shared.b16 {%0,%1,%2,%3}, [%4];"
                 : "=r"(r[0]), "=r"(r[1]), "=r"(r[2]), "=r"(r[3]) : "r"(addr));
}
__device__ __forceinline__ void mma_bf16(float* d, const uint32_t* a, const uint32_t* b) {
    asm volatile(
        "mma.sync.aligned.m16n8k16.row.col.f32.bf16.bf16.f32 "
        "{%0,%1,%2,%3}, {%4,%5,%6,%7}, {%8,%9}, {%0,%1,%2,%3};"
        : "+f"(d[0]), "+f"(d[1]), "+f"(d[2]), "+f"(d[3])
        : "r"(a[0]), "r"(a[1]), "r"(a[2]), "r"(a[3]), "r"(b[0]), "r"(b[1]));
}

// bulk async copy (UBLKCP) — sm_90 baseline PTX, fine on compute_103
__device__ __forceinline__ void bulk_ld(uint32_t dst, const void* src, uint32_t bytes,
                                        uint32_t mbar) {
    asm volatile(
        "cp.async.bulk.shared::cluster.global.mbarrier::complete_tx::bytes [%0], [%1], %2, [%3];"
        :: "r"(dst), "l"(src), "r"(bytes), "r"(mbar) : "memory");
}
#define MBAR_INIT(a, c)   asm volatile("mbarrier.init.shared.b64 [%0], %1;" :: "r"(a), "r"(c) : "memory")
#define MBAR_EXPECT(a, n) asm volatile("mbarrier.arrive.expect_tx.shared.b64 _, [%0], %1;" :: "r"(a), "r"(n) : "memory")
#define FENCE_ASYNC()     asm volatile("fence.proxy.async.shared::cta;" ::: "memory")
#define MBAR_WAIT(a, ph) do {                                                   \
    uint32_t _m = (a), _p = (ph), _d;                                           \
    asm volatile("{\n\t.reg .pred p;\n\t"                                       \
        "mbarrier.try_wait.parity.acquire.cta.shared::cta.b64 p, [%1], %2;\n\t" \
        "selp.b32 %0, 1, 0, p;\n\t}" : "=r"(_d) : "r"(_m), "r"(_p) : "memory"); \
    if (!_d) {                                                                  \
        asm volatile("{\n\t.reg .pred P1;\n\tWL_%=: \n\t"                       \
            "mbarrier.try_wait.parity.acquire.cta.shared::cta.b64 P1, [%0], %1, 0x989680;\n\t" \
            "@P1 bra.uni WD_%=;\n\tbra.uni WL_%=;\n\tWD_%=:\n\t}"               \
            :: "r"(_m), "r"(_p) : "memory");                                    \
    }                                                                           \
} while (0)

// ---------------------------------------------------------------------------
// Split + pack conversions.  Packed byte address for (chunk, row, inner byte):
//   ((chunk*rows + row)*128) + (ib ^ ((row&7)<<4))
// ---------------------------------------------------------------------------
__device__ __forceinline__ void split4(const float4 v, uint2& hv, uint2& lv) {
    __nv_bfloat16 h0 = __float2bfloat16(v.x), h1 = __float2bfloat16(v.y);
    __nv_bfloat16 h2 = __float2bfloat16(v.z), h3 = __float2bfloat16(v.w);
    __nv_bfloat16 l0 = __float2bfloat16(v.x - __bfloat162float(h0));
    __nv_bfloat16 l1 = __float2bfloat16(v.y - __bfloat162float(h1));
    __nv_bfloat16 l2 = __float2bfloat16(v.z - __bfloat162float(h2));
    __nv_bfloat16 l3 = __float2bfloat16(v.w - __bfloat162float(h3));
    hv.x = (uint32_t)__bfloat16_as_ushort(h0) | ((uint32_t)__bfloat16_as_ushort(h1) << 16);
    hv.y = (uint32_t)__bfloat16_as_ushort(h2) | ((uint32_t)__bfloat16_as_ushort(h3) << 16);
    lv.x = (uint32_t)__bfloat16_as_ushort(l0) | ((uint32_t)__bfloat16_as_ushort(l1) << 16);
    lv.y = (uint32_t)__bfloat16_as_ushort(l2) | ((uint32_t)__bfloat16_as_ushort(l3) << 16);
}

__device__ __forceinline__ void pack_store8(char* basep, size_t rows, int chunk,
                                            size_t row, int ib, uint2 v) {
    size_t off = ((size_t)chunk * rows + row) * 128 + (size_t)(ib ^ (((int)row & 7) << 4));
    *(uint2*)(basep + off) = v;
}

// x -> packed hi/lo (rows = MM); m0 selects half
__global__ __launch_bounds__(256)
void cvt_x_pack(const float* __restrict__ x, int m0)
{
    int i = blockIdx.x * 256 + threadIdx.x;
    size_t m = (size_t)m0 + (i >> 8);
    int j = i & 255, k0 = j * 4;
    uint2 hv, lv;
    split4(*(const float4*)(x + m * DIMM + k0), hv, lv);
    int chunk = k0 >> 6, ib = (k0 & 63) * 2;
    pack_store8((char*)g_xhi, MM, chunk, m, ib, hv);
    pack_store8((char*)g_xlo, MM, chunk, m, ib, lv);
}

// 4 big weights -> packed (rows = 1024)
__global__ __launch_bounds__(256)
void cvt_w_pack(const float* __restrict__ Wq, const float* __restrict__ Wk,
                const float* __restrict__ Wv, const float* __restrict__ Wo)
{
    const int z = blockIdx.y;
    const float* src = (z == 0) ? Wq : (z == 1) ? Wk : (z == 2) ? Wv : Wo;
    char* hi = (char*)((z == 0) ? g_wq_hi : (z == 1) ? g_wk_hi : (z == 2) ? g_wv_hi : g_wo_hi);
    char* lo = (char*)((z == 0) ? g_wq_lo : (z == 1) ? g_wk_lo : (z == 2) ? g_wv_lo : g_wo_lo);
    int i = blockIdx.x * 256 + threadIdx.x;
    size_t n = i >> 8;
    int j = i & 255, k0 = j * 4;
    uint2 hv, lv;
    split4(*(const float4*)(src + n * DIMM + k0), hv, lv);
    int chunk = k0 >> 6, ib = (k0 & 63) * 2;
    pack_store8(hi, DIMM, chunk, n, ib, hv);
    pack_store8(lo, DIMM, chunk, n, ib, lv);
}

// gate weights -> packed concat (rows = 32): z=0 Wa rows 0..15, z=1 Wb rows 16..31
__global__ __launch_bounds__(256)
void cvt_ab_pack(const float* __restrict__ Wa, const float* __restrict__ Wb)
{
    const int z = blockIdx.y;
    const float* src = z ? Wb : Wa;
    int i = blockIdx.x * 256 + threadIdx.x;
    size_t nl = i >> 8;
    size_t n = z * 16 + nl;
    int j = i & 255, k0 = j * 4;
    uint2 hv, lv;
    split4(*(const float4*)(src + nl * DIMM + k0), hv, lv);
    int chunk = k0 >> 6, ib = (k0 & 63) * 2;
    pack_store8((char*)g_wab_hi, 32, chunk, n, ib, hv);
    pack_store8((char*)g_wab_lo, 32, chunk, n, ib, lv);
}

// ---------------------------------------------------------------------------
// Big HMMA GEMM, bulk-copy fed. CTA tile 256x128, warp tile 64x64, K chunk 64,
// 2-stage pipeline (mbarrier + cp.async.bulk), bf16 3-pass split.
// MODE 0: QKV merged (wsel = blockIdx.x>>3) -> SiLU -> g_{q,k,v}lin.
// MODE 1: O projection -> Cout.
// ---------------------------------------------------------------------------
template<int MODE>
__global__ __launch_bounds__(256, 1)
void hmma_big(const float* __restrict__ bias_q, const float* __restrict__ bias_k,
              const float* __restrict__ bias_v, float* __restrict__ Cout)
{
    extern __shared__ char smraw[];
    uint32_t base = (smem_u32(smraw) + 1023u) & ~1023u;

    constexpr int ATILE = 256 * 128;   // 32KB
    constexpr int BTILE = 128 * 128;   // 16KB
    constexpr int STG   = 2 * ATILE + 2 * BTILE;   // 96KB
    const uint32_t mb0 = base + 2 * STG;
    const uint32_t mb1 = base + 2 * STG + 8;

    const char *Ah, *Al, *Bh, *Bl;
    const float* bias;
    float* C;
    int bn_idx;
    if (MODE == 0) {
        const int wsel = blockIdx.x >> 3;
        bn_idx = blockIdx.x & 7;
        Ah = (const char*)g_xhi; Al = (const char*)g_xlo;
        Bh   = (const char*)((wsel == 0) ? g_wq_hi : (wsel == 1) ? g_wk_hi : g_wv_hi);
        Bl   = (const char*)((wsel == 0) ? g_wq_lo : (wsel == 1) ? g_wk_lo : g_wv_lo);
        bias = (wsel == 0) ? bias_q : (wsel == 1) ? bias_k : bias_v;
        C    = (wsel == 0) ? g_qlin : (wsel == 1) ? g_klin : g_vlin;
    } else {
        bn_idx = blockIdx.x;
        Ah = (const char*)g_ohi; Al = (const char*)g_olo;
        Bh = (const char*)g_wo_hi; Bl = (const char*)g_wo_lo;
        bias = bias_q; C = Cout;
    }

    const int tid = threadIdx.x;
    const int wid = tid >> 5;
    const int lid = tid & 31;
    const int bm = blockIdx.y * 256;
    const int bn = bn_idx * 128;

    const int warp_m0 = (wid & 3) * 64;
    const int warp_n0 = (wid >> 2) * 64;
    const int a_row = lid & 15;
    const int a_sel = lid >> 4;
    const int b_row = (lid & 7) + ((lid >> 4) << 3);
    const int b_sel = (lid >> 3) & 1;

    if (tid == 0) { MBAR_INIT(mb0, 1); MBAR_INIT(mb1, 1); }
    __syncthreads();

    if (tid == 0) {
        FENCE_ASYNC();
#pragma unroll
        for (int c = 0; c < 2; c++) {
            uint32_t st = base + c * STG;
            uint32_t mb = c ? mb1 : mb0;
            MBAR_EXPECT(mb, (uint32_t)STG);
            bulk_ld(st,                     Ah + ((size_t)c * MM + bm) * 128,   ATILE, mb);
            bulk_ld(st + ATILE,             Al + ((size_t)c * MM + bm) * 128,   ATILE, mb);
            bulk_ld(st + 2 * ATILE,         Bh + ((size_t)c * DIMM + bn) * 128, BTILE, mb);
            bulk_ld(st + 2 * ATILE + BTILE, Bl + ((size_t)c * DIMM + bn) * 128, BTILE, mb);
        }
    }

    float acc[4][8][4];
#pragma unroll
    for (int mi = 0; mi < 4; mi++)
#pragma unroll
        for (int ni = 0; ni < 8; ni++)
#pragma unroll
            for (int j = 0; j < 4; j++) acc[mi][ni][j] = 0.f;

    uint32_t ph0 = 0, ph1 = 0;

    for (int c = 0; c < 16; c++) {
        const int s = c & 1;
        const uint32_t st = base + s * STG;
        if (s) { MBAR_WAIT(mb1, ph1); ph1 ^= 1; }
        else   { MBAR_WAIT(mb0, ph0); ph0 ^= 1; }

        const uint32_t sAh = st, sAl = st + ATILE;
        const uint32_t sBh = st + 2 * ATILE, sBl = st + 2 * ATILE + BTILE;

#pragma unroll
        for (int ks = 0; ks < 4; ks++) {
            uint32_t bh[8][2], bl[8][2];
#pragma unroll
            for (int j = 0; j < 4; j++) {
                uint32_t off = (uint32_t)(warp_n0 + j * 16 + b_row) * 128 + ks * 32 + b_sel * 16;
                uint32_t sw = SWZ128(off);
                uint32_t t4[4];
                ldsm4(t4, sBh + sw);
                bh[2*j][0] = t4[0]; bh[2*j][1] = t4[1];
                bh[2*j+1][0] = t4[2]; bh[2*j+1][1] = t4[3];
                ldsm4(t4, sBl + sw);
                bl[2*j][0] = t4[0]; bl[2*j][1] = t4[1];
                bl[2*j+1][0] = t4[2]; bl[2*j+1][1] = t4[3];
            }
#pragma unroll
            for (int mi = 0; mi < 4; mi++) {
                uint32_t ah[4], al[4];
                uint32_t off = (uint32_t)(warp_m0 + mi * 16 + a_row) * 128 + ks * 32 + a_sel * 16;
                uint32_t sw = SWZ128(off);
                ldsm4(ah, sAh + sw);
                ldsm4(al, sAl + sw);
#pragma unroll
                for (int ni = 0; ni < 8; ni++) {
                    mma_bf16(acc[mi][ni], ah, bh[ni]);
                    mma_bf16(acc[mi][ni], ah, bl[ni]);
                    mma_bf16(acc[mi][ni], al, bh[ni]);
                }
            }
        }
        __syncthreads();

        if (c + 2 < 16 && tid == 0) {
            const int cn = c + 2;
            const uint32_t mb = s ? mb1 : mb0;
            MBAR_EXPECT(mb, (uint32_t)STG);
            bulk_ld(st,                     Ah + ((size_t)cn * MM + bm) * 128,   ATILE, mb);
            bulk_ld(st + ATILE,             Al + ((size_t)cn * MM + bm) * 128,   ATILE, mb);
            bulk_ld(st + 2 * ATILE,         Bh + ((size_t)cn * DIMM + bn) * 128, BTILE, mb);
            bulk_ld(st + 2 * ATILE + BTILE, Bl + ((size_t)cn * DIMM + bn) * 128, BTILE, mb);
        }
    }

    // epilogue
#pragma unroll
    for (int mi = 0; mi < 4; mi++) {
        int r0 = bm + warp_m0 + mi * 16 + (lid >> 2);
        int r1 = r0 + 8;
#pragma unroll
        for (int ni = 0; ni < 8; ni++) {
            int col = bn + warp_n0 + ni * 8 + (lid & 3) * 2;
            float bx = __ldg(&bias[col]), by = __ldg(&bias[col + 1]);
            float v0 = acc[mi][ni][0] + bx, v1 = acc[mi][ni][1] + by;
            float v2 = acc[mi][ni][2] + bx, v3 = acc[mi][ni][3] + by;
            if (MODE == 0) { v0 = siluf_(v0); v1 = siluf_(v1); v2 = siluf_(v2); v3 = siluf_(v3); }
            *(float2*)&C[(size_t)r0 * DIMM + col] = make_float2(v0, v1);
            *(float2*)&C[(size_t)r1 * DIMM + col] = make_float2(v2, v3);
        }
    }
}

// ---------------------------------------------------------------------------
// Gate GEMM (N=32), bulk-fed: sigmoid(x@Wab^T + b) -> g_a / g_bg
// 8 m-warps, warp tile 16x32.
// ---------------------------------------------------------------------------
__global__ __launch_bounds__(256, 1)
void hmma_gate(const float* __restrict__ ba, const float* __restrict__ bb)
{
    extern __shared__ char smraw[];
    uint32_t base = (smem_u32(smraw) + 1023u) & ~1023u;

    constexpr int ATILE = 128 * 128;  // 16KB
    constexpr int BTILE = 32 * 128;   // 4KB
    constexpr int STG   = 2 * ATILE + 2 * BTILE;  // 40KB
    const uint32_t mb0 = base + 2 * STG;
    const uint32_t mb1 = base + 2 * STG + 8;

    const int tid = threadIdx.x;
    const int wid = tid >> 5;
    const int lid = tid & 31;
    const int bm = blockIdx.y * 128;

    const int warp_m0 = wid * 16;
    const int a_row = lid & 15;
    const int a_sel = lid >> 4;
    const int b_row = (lid & 7) + ((lid >> 4) << 3);
    const int b_sel = (lid >> 3) & 1;

    if (tid == 0) { MBAR_INIT(mb0, 1); MBAR_INIT(mb1, 1); }
    __syncthreads();

    if (tid == 0) {
        FENCE_ASYNC();
#pragma unroll
        for (int c = 0; c < 2; c++) {
            uint32_t st = base + c * STG;
            uint32_t mb = c ? mb1 : mb0;
            MBAR_EXPECT(mb, (uint32_t)STG);
            bulk_ld(st,                     (const char*)g_xhi   + ((size_t)c * MM + bm) * 128, ATILE, mb);
            bulk_ld(st + ATILE,             (const char*)g_xlo   + ((size_t)c * MM + bm) * 128, ATILE, mb);
            bulk_ld(st + 2 * ATILE,         (const char*)g_wab_hi + (size_t)c * 32 * 128,       BTILE, mb);
            bulk_ld(st + 2 * ATILE + BTILE, (const char*)g_wab_lo + (size_t)c * 32 * 128,       BTILE, mb);
        }
    }

    float acc[4][4];
#pragma unroll
    for (int ni = 0; ni < 4; ni++)
#pragma unroll
        for (int j = 0; j < 4; j++) acc[ni][j] = 0.f;

    uint32_t ph0 = 0, ph1 = 0;

    for (int c = 0; c < 16; c++) {
        const int s = c & 1;
        const uint32_t st = base + s * STG;
        if (s) { MBAR_WAIT(mb1, ph1); ph1 ^= 1; }
        else   { MBAR_WAIT(mb0, ph0); ph0 ^= 1; }

        const uint32_t sAh = st, sAl = st + ATILE;
        const uint32_t sBh = st + 2 * ATILE, sBl = st + 2 * ATILE + BTILE;

#pragma unroll
        for (int ks = 0; ks < 4; ks++) {
            uint32_t ah[4], al[4];
            {
                uint32_t off = (uint32_t)(warp_m0 + a_row) * 128 + ks * 32 + a_sel * 16;
                uint32_t sw = SWZ128(off);
                ldsm4(ah, sAh + sw);
                ldsm4(al, sAl + sw);
            }
            uint32_t bh[4][2], bl[4][2];
#pragma unroll
            for (int j = 0; j < 2; j++) {
                uint32_t off = (uint32_t)(j * 16 + b_row) * 128 + ks * 32 + b_sel * 16;
                uint32_t sw = SWZ128(off);
                uint32_t t4[4];
                ldsm4(t4, sBh + sw);
                bh[2*j][0] = t4[0]; bh[2*j][1] = t4[1];
                bh[2*j+1][0] = t4[2]; bh[2*j+1][1] = t4[3];
                ldsm4(t4, sBl + sw);
                bl[2*j][0] = t4[0]; bl[2*j][1] = t4[1];
                bl[2*j+1][0] = t4[2]; bl[2*j+1][1] = t4[3];
            }
#pragma unroll
            for (int ni = 0; ni < 4; ni++) {
                mma_bf16(acc[ni], ah, bh[ni]);
                mma_bf16(acc[ni], ah, bl[ni]);
                mma_bf16(acc[ni], al, bh[ni]);
            }
        }
        __syncthreads();

        if (c + 2 < 16 && tid == 0) {
            const int cn = c + 2;
            const uint32_t mb = s ? mb1 : mb0;
            MBAR_EXPECT(mb, (uint32_t)STG);
            bulk_ld(st,                     (const char*)g_xhi   + ((size_t)cn * MM + bm) * 128, ATILE, mb);
            bulk_ld(st + ATILE,             (const char*)g_xlo   + ((size_t)cn * MM + bm) * 128, ATILE, mb);
            bulk_ld(st + 2 * ATILE,         (const char*)g_wab_hi + (size_t)cn * 32 * 128,       BTILE, mb);
            bulk_ld(st + 2 * ATILE + BTILE, (const char*)g_wab_lo + (size_t)cn * 32 * 128,       BTILE, mb);
        }
    }

    const int r0 = bm + warp_m0 + (lid >> 2);
#pragma unroll
    for (int ni = 0; ni < 4; ni++) {
        int col = ni * 8 + (lid & 3) * 2;
        float bx = (col < 16) ? __ldg(&ba[col])     : __ldg(&bb[col - 16]);
        float by = (col < 16) ? __ldg(&ba[col + 1]) : __ldg(&bb[col - 15]);
        float* dst = (col < 16) ? g_a : g_bg;
        int cc = (col < 16) ? col : col - 16;
        float2 v0 = { sigmoidf_(acc[ni][0] + bx), sigmoidf_(acc[ni][1] + by) };
        float2 v1 = { sigmoidf_(acc[ni][2] + bx), sigmoidf_(acc[ni][3] + by) };
        *(float2*)&dst[(size_t)r0 * HH + cc] = v0;
        *(float2*)&dst[(size_t)(r0 + 8) * HH + cc] = v1;
    }
}

// ---------------------------------------------------------------------------
// Depthwise conv (K=4, pad=2, truncated) + SiLU + optional L2 norm
// ---------------------------------------------------------------------------
__global__ __launch_bounds__(256)
void conv_norm_kernel(const float* __restrict__ wq, const float* __restrict__ wk,
                      const float* __restrict__ wv)
{
    const int z = blockIdx.y;
    const float* __restrict__ in  = (z == 0) ? g_qlin : (z == 1) ? g_klin : g_vlin;
    const float* __restrict__ w   = (z == 0) ? wq     : (z == 1) ? wk     : wv;
    float* __restrict__ out       = (z == 0) ? g_q    : (z == 1) ? g_k    : g_v;

    const int bt = blockIdx.x;
    const int b = bt / NN;
    const int t = bt % NN;
    const int tid = threadIdx.x;
    const int c0 = tid * 4;

    float4 w0 = *(const float4*)(w + c0 * 4 + 0);
    float4 w1 = *(const float4*)(w + c0 * 4 + 4);
    float4 w2 = *(const float4*)(w + c0 * 4 + 8);
    float4 w3 = *(const float4*)(w + c0 * 4 + 12);
    float wc[4][4] = {{w0.x,w0.y,w0.z,w0.w},{w1.x,w1.y,w1.z,w1.w},
                      {w2.x,w2.y,w2.z,w2.w},{w3.x,w3.y,w3.z,w3.w}};

    float y[4] = {0.f, 0.f, 0.f, 0.f};
#pragma unroll
    for (int j = 0; j < 4; j++) {
        int tt = t + j - 2;
        if (tt >= 0 && tt < NN) {
            float4 xv = *(const float4*)(in + ((size_t)b * NN + tt) * DIMM + c0);
            y[0] += xv.x * wc[0][j];
            y[1] += xv.y * wc[1][j];
            y[2] += xv.z * wc[2][j];
            y[3] += xv.w * wc[3][j];
        }
    }
#pragma unroll
    for (int m = 0; m < 4; m++) y[m] = siluf_(y[m]);

    float ss = y[0]*y[0] + y[1]*y[1] + y[2]*y[2] + y[3]*y[3];
#pragma unroll
    for (int off = 16; off; off >>= 1) ss += __shfl_down_sync(0xffffffffu, ss, off);
    __shared__ float wss[8];
    __shared__ float inv_sh;
    const int lane = tid & 31, widx = tid >> 5;
    if (lane == 0) wss[widx] = ss;
    __syncthreads();
    if (tid == 0) {
        float tot = 0.f;
#pragma unroll
        for (int i = 0; i < 8; i++) tot += wss[i];
        inv_sh = 1.f / (sqrtf(tot) + EPSF);
    }
    __syncthreads();
    float inv = (z < 2) ? inv_sh : 1.f;

    float4 ov; ov.x = y[0]*inv; ov.y = y[1]*inv; ov.z = y[2]*inv; ov.w = y[3]*inv;
    *(float4*)(out + ((size_t)b * NN + t) * DIMM + c0) = ov;
}

// ---------------------------------------------------------------------------
// Gated delta-rule scan, dual-state (S + S^T), 128 threads per (b,h).
// Group1 writes O directly into the packed hi/lo layout (chunk index = h).
// ---------------------------------------------------------------------------
__global__ __launch_bounds__(128)
void scan_kernel()
{
    const int bh = blockIdx.x;
    const int b = bh >> 4;
    const int h = bh & 15;
    const int tid = threadIdx.x;

    __shared__ __align__(16) float k_sh[2][64];
    __shared__ __align__(16) float q_sh[2][64];
    __shared__ __align__(16) float coef_sh[64];

    const size_t gb = ((size_t)b * NN) * HH + h;

    if (tid < 64) {
        const int d = tid;
        const size_t base = ((size_t)b * NN) * DIMM + h * DHH + d;
        float S[64];
#pragma unroll
        for (int e = 0; e < 64; e++) S[e] = 0.f;
        float vc = g_v[base], ac = g_a[gb], bc = g_bg[gb];
        __syncthreads();

        for (int t = 0; t < NN; t++) {
            const float4* kb = (const float4*)k_sh[t & 1];
            float sk0 = 0.f, sk1 = 0.f, sk2 = 0.f, sk3 = 0.f;
#pragma unroll
            for (int i = 0; i < 16; i++) {
                float4 kv = kb[i];
                sk0 += S[4*i+0] * kv.x; sk1 += S[4*i+1] * kv.y;
                sk2 += S[4*i+2] * kv.z; sk3 += S[4*i+3] * kv.w;
            }
            float coef = bc * vc - ac * bc * ((sk0 + sk1) + (sk2 + sk3));
            coef_sh[d] = coef;
            float vn = 0.f, an = 0.f, bn = 0.f;
            if (t + 1 < NN) {
                vn = g_v[base + (size_t)(t + 1) * DIMM];
                an = g_a[gb + (size_t)(t + 1) * HH];
                bn = g_bg[gb + (size_t)(t + 1) * HH];
            }
            __syncthreads();
            float av = ac;
#pragma unroll
            for (int i = 0; i < 16; i++) {
                float4 kv = kb[i];
                S[4*i+0] = av * S[4*i+0] + coef * kv.x;
                S[4*i+1] = av * S[4*i+1] + coef * kv.y;
                S[4*i+2] = av * S[4*i+2] + coef * kv.z;
                S[4*i+3] = av * S[4*i+3] + coef * kv.w;
            }
            vc = vn; ac = an; bc = bn;
            __syncthreads();
        }
    } else {
        const int e = tid - 64;
        const size_t base = ((size_t)b * NN) * DIMM + h * DHH + e;
        float T[64];
#pragma unroll
        for (int d = 0; d < 64; d++) T[d] = 0.f;
        float kc = g_k[base];
        float qc = g_q[base];
        k_sh[0][e] = kc;
        q_sh[0][e] = qc;
        float ac = g_a[gb];
        float kn = 0.f, qn = 0.f;
        if (NN > 1) { kn = g_k[base + DIMM]; qn = g_q[base + DIMM]; }
        __syncthreads();

        for (int t = 0; t < NN; t++) {
            const int buf = t & 1;
            float an = 0.f, kn2 = 0.f, qn2 = 0.f;
            if (t + 1 < NN) an = g_a[gb + (size_t)(t + 1) * HH];
            if (t + 2 < NN) {
                kn2 = g_k[base + (size_t)(t + 2) * DIMM];
                qn2 = g_q[base + (size_t)(t + 2) * DIMM];
            }
            __syncthreads();
            const float av = ac;
            const float4* cf4 = (const float4*)coef_sh;
            const float4* qb  = (const float4*)q_sh[buf];
            float o0 = 0.f, o1 = 0.f, o2 = 0.f, o3 = 0.f;
#pragma unroll
            for (int i = 0; i < 16; i++) {
                float4 cf = cf4[i];
                float4 qv = qb[i];
                float t0 = av * T[4*i+0] + cf.x * kc; T[4*i+0] = t0; o0 += t0 * qv.x;
                float t1 = av * T[4*i+1] + cf.y * kc; T[4*i+1] = t1; o1 += t1 * qv.y;
                float t2 = av * T[4*i+2] + cf.z * kc; T[4*i+2] = t2; o2 += t2 * qv.z;
                float t3 = av * T[4*i+3] + cf.w * kc; T[4*i+3] = t3; o3 += t3 * qv.w;
            }
            float o = (o0 + o1) + (o2 + o3);
            __nv_bfloat16 hi = __float2bfloat16(o);
            __nv_bfloat16 lo = __float2bfloat16(o - __bfloat162float(hi));
            // packed write: chunk = h, row m = b*NN+t, inner byte = e*2
            size_t m = (size_t)b * NN + t;
            size_t off = ((size_t)h * MM + m) * 128 + (size_t)((e * 2) ^ (((int)m & 7) << 4));
            *(__nv_bfloat16*)((char*)g_ohi + off) = hi;
            *(__nv_bfloat16*)((char*)g_olo + off) = lo;
            if (t + 1 < NN) {
                k_sh[buf ^ 1][e] = kn;
                q_sh[buf ^ 1][e] = qn;
            }
            kc = kn; kn = kn2; qn = qn2; ac = an;
            __syncthreads();
        }
    }
}

// ---------------------------------------------------------------------------
// Launch (ncu profiles my launch index 3 -> put QKV GEMM there)
// ---------------------------------------------------------------------------
extern "C" void kernel_launch(void* const* d_in, const int* in_sizes, int n_in,
                              void* d_out, int out_size)
{
    (void)in_sizes; (void)n_in; (void)out_size;
    const float* x      = (const float*)d_in[0];
    const float* Wq     = (const float*)d_in[1];
    const float* bq     = (const float*)d_in[2];
    const float* Wk     = (const float*)d_in[3];
    const float* bk     = (const float*)d_in[4];
    const float* Wv     = (const float*)d_in[5];
    const float* bv     = (const float*)d_in[6];
    const float* Wa     = (const float*)d_in[7];
    const float* ba     = (const float*)d_in[8];
    const float* Wb     = (const float*)d_in[9];
    const float* bb     = (const float*)d_in[10];
    const float* conv_q = (const float*)d_in[11];
    const float* conv_k = (const float*)d_in[12];
    const float* conv_v = (const float*)d_in[13];
    const float* Wo     = (const float*)d_in[14];
    const float* bo     = (const float*)d_in[15];
    float* out = (float*)d_out;

    const int smem_big  = 1024 + 2 * (2 * 256 * 128 + 2 * 128 * 128) + 64;  // ~197KB
    const int smem_gate = 1024 + 2 * (2 * 128 * 128 + 2 * 32 * 128) + 64;   // ~81KB
    cudaFuncSetAttribute(hmma_big<0>, cudaFuncAttributeMaxDynamicSharedMemorySize, smem_big);
    cudaFuncSetAttribute(hmma_big<1>, cudaFuncAttributeMaxDynamicSharedMemorySize, smem_big);
    cudaFuncSetAttribute(hmma_gate,   cudaFuncAttributeMaxDynamicSharedMemorySize, smem_gate);

    // [0],[1]: x conversion+pack in two halves
    cvt_x_pack<<<MM / 2, 256>>>(x, 0);
    cvt_x_pack<<<MM / 2, 256>>>(x, MM / 2);
    // [2]: big weights pack
    cvt_w_pack<<<dim3(DIMM, 4), 256>>>(Wq, Wk, Wv, Wo);
    // [3]: merged QKV GEMM  <-- ncu capture lands here
    hmma_big<0><<<dim3(24, 64), 256, smem_big>>>(bq, bk, bv, nullptr);
    // [4]: gate weights pack
    cvt_ab_pack<<<dim3(16, 2), 256>>>(Wa, Wb);
    // [5]: gates
    hmma_gate<<<dim3(1, 128), 256, smem_gate>>>(ba, bb);
    // [6]: conv + norm
    conv_norm_kernel<<<dim3(MM, 3), 256>>>(conv_q, conv_k, conv_v);
    // [7]: scan (writes O packed)
    scan_kernel<<<BB * HH, 128>>>();
    // [8]: output projection
    hmma_big<1><<<dim3(8, 64), 256, smem_big>>>(bo, nullptr, nullptr, out);
}

// round 9
// speedup vs baseline: 2.6619x; 1.2712x over previous
#include <cuda_runtime.h>
#include <cuda_fp16.h>
#include <cstdint>

// Problem constants
#define BB   8
#define NN   2048
#define DIMM 1024
#define HH   16
#define DHH  64
#define MM   (BB*NN)          // 16384 rows
#define EPSF 1e-6f

typedef unsigned long long ull_t;

// ---------------------------------------------------------------------------
// Scratch (device globals; no allocation allowed)
// ---------------------------------------------------------------------------
__device__ float g_qlin[BB*NN*DIMM];
__device__ float g_klin[BB*NN*DIMM];
__device__ float g_vlin[BB*NN*DIMM];
__device__ float g_q[BB*NN*DIMM];
__device__ float g_k[BB*NN*DIMM];
__device__ float g_v[BB*NN*DIMM];
__device__ float g_a[BB*NN*HH];
__device__ float g_bg[BB*NN*HH];

// chunk-packed, pre-swizzled fp16 operands: [c][row][128B], inner byte xor
// (ib ^ ((row&7)<<4)) baked in.
__device__ __half g_xh[MM*DIMM];
__device__ __half g_oh[MM*DIMM];
__device__ __half g_wq[DIMM*DIMM];
__device__ __half g_wk[DIMM*DIMM];
__device__ __half g_wv[DIMM*DIMM];
__device__ __half g_wo[DIMM*DIMM];
__device__ __half g_wab[32*DIMM];

__device__ __forceinline__ float sigmoidf_(float x) { return 1.f / (1.f + __expf(-x)); }
__device__ __forceinline__ float siluf_(float x)    { return x / (1.f + __expf(-x)); }

// ---------------------------------------------------------------------------
// PTX helpers
// ---------------------------------------------------------------------------
__device__ __forceinline__ uint32_t smem_u32(const void* p) {
    uint32_t a;
    asm("{ .reg .u64 t; cvta.to.shared.u64 t, %1; cvt.u32.u64 %0, t; }" : "=r"(a) : "l"(p));
    return a;
}
#define SWZ128(o) ((o) ^ (((o) >> 3) & 0x70))

__device__ __forceinline__ void ldsm4(uint32_t* r, uint32_t addr) {
    asm volatile("ldmatrix.sync.aligned.m8n8.x4.shared.b16 {%0,%1,%2,%3}, [%4];"
                 : "=r"(r[0]), "=r"(r[1]), "=r"(r[2]), "=r"(r[3]) : "r"(addr));
}
__device__ __forceinline__ void mma_f16(float* d, const uint32_t* a, const uint32_t* b) {
    asm volatile(
        "mma.sync.aligned.m16n8k16.row.col.f32.f16.f16.f32 "
        "{%0,%1,%2,%3}, {%4,%5,%6,%7}, {%8,%9}, {%0,%1,%2,%3};"
        : "+f"(d[0]), "+f"(d[1]), "+f"(d[2]), "+f"(d[3])
        : "r"(a[0]), "r"(a[1]), "r"(a[2]), "r"(a[3]), "r"(b[0]), "r"(b[1]));
}

__device__ __forceinline__ void bulk_ld(uint32_t dst, const void* src, uint32_t bytes,
                                        uint32_t mbar) {
    asm volatile(
        "cp.async.bulk.shared::cluster.global.mbarrier::complete_tx::bytes [%0], [%1], %2, [%3];"
        :: "r"(dst), "l"(src), "r"(bytes), "r"(mbar) : "memory");
}
#define MBAR_INIT(a, c)   asm volatile("mbarrier.init.shared.b64 [%0], %1;" :: "r"(a), "r"(c) : "memory")
#define MBAR_EXPECT(a, n) asm volatile("mbarrier.arrive.expect_tx.shared.b64 _, [%0], %1;" :: "r"(a), "r"(n) : "memory")
#define FENCE_ASYNC()     asm volatile("fence.proxy.async.shared::cta;" ::: "memory")
#define MBAR_WAIT(a, ph) do {                                                   \
    uint32_t _m = (a), _p = (ph), _d;                                           \
    asm volatile("{\n\t.reg .pred p;\n\t"                                       \
        "mbarrier.try_wait.parity.acquire.cta.shared::cta.b64 p, [%1], %2;\n\t" \
        "selp.b32 %0, 1, 0, p;\n\t}" : "=r"(_d) : "r"(_m), "r"(_p) : "memory"); \
    if (!_d) {                                                                  \
        asm volatile("{\n\t.reg .pred P1;\n\tWL_%=: \n\t"                       \
            "mbarrier.try_wait.parity.acquire.cta.shared::cta.b64 P1, [%0], %1, 0x989680;\n\t" \
            "@P1 bra.uni WD_%=;\n\tbra.uni WL_%=;\n\tWD_%=:\n\t}"               \
            :: "r"(_m), "r"(_p) : "memory");                                    \
    }                                                                           \
} while (0)

// packed f32x2 (PTX 8.6, sm_100+ family)
#define FMA2(d, a, b, c) asm("fma.rn.f32x2 %0, %1, %2, %3;" : "=l"(d) : "l"(a), "l"(b), "l"(c))
#define MUL2(d, a, b)    asm("mul.rn.f32x2 %0, %1, %2;"     : "=l"(d) : "l"(a), "l"(b))
__device__ __forceinline__ ull_t pack2(float x, float y) {
    ull_t r; asm("mov.b64 %0, {%1, %2};" : "=l"(r) : "f"(x), "f"(y)); return r;
}
__device__ __forceinline__ void unpack2(ull_t v, float& x, float& y) {
    asm("mov.b64 {%0, %1}, %2;" : "=f"(x), "=f"(y) : "l"(v));
}

// ---------------------------------------------------------------------------
// fp16 pack conversions.  Packed byte address for (chunk, row, inner byte ib):
//   ((chunk*rows + row)*128) + (ib ^ ((row&7)<<4))
// ---------------------------------------------------------------------------
__device__ __forceinline__ uint2 cvt4h(const float4 v) {
    uint2 r;
    r.x = (uint32_t)__half_as_ushort(__float2half_rn(v.x))
        | ((uint32_t)__half_as_ushort(__float2half_rn(v.y)) << 16);
    r.y = (uint32_t)__half_as_ushort(__float2half_rn(v.z))
        | ((uint32_t)__half_as_ushort(__float2half_rn(v.w)) << 16);
    return r;
}
__device__ __forceinline__ void pack_store8(char* basep, size_t rows, int chunk,
                                            size_t row, int ib, uint2 v) {
    size_t off = ((size_t)chunk * rows + row) * 128 + (size_t)(ib ^ (((int)row & 7) << 4));
    *(uint2*)(basep + off) = v;
}

__global__ __launch_bounds__(256)
void cvt_x_pack(const float* __restrict__ x, int m0)
{
    int i = blockIdx.x * 256 + threadIdx.x;
    size_t m = (size_t)m0 + (i >> 8);
    int j = i & 255, k0 = j * 4;
    uint2 hv = cvt4h(*(const float4*)(x + m * DIMM + k0));
    pack_store8((char*)g_xh, MM, k0 >> 6, m, (k0 & 63) * 2, hv);
}

__global__ __launch_bounds__(256)
void cvt_w_pack(const float* __restrict__ Wq, const float* __restrict__ Wk,
                const float* __restrict__ Wv, const float* __restrict__ Wo)
{
    const int z = blockIdx.y;
    const float* src = (z == 0) ? Wq : (z == 1) ? Wk : (z == 2) ? Wv : Wo;
    char* dst = (char*)((z == 0) ? g_wq : (z == 1) ? g_wk : (z == 2) ? g_wv : g_wo);
    int i = blockIdx.x * 256 + threadIdx.x;
    size_t n = i >> 8;
    int j = i & 255, k0 = j * 4;
    uint2 hv = cvt4h(*(const float4*)(src + n * DIMM + k0));
    pack_store8(dst, DIMM, k0 >> 6, n, (k0 & 63) * 2, hv);
}

__global__ __launch_bounds__(256)
void cvt_ab_pack(const float* __restrict__ Wa, const float* __restrict__ Wb)
{
    const int z = blockIdx.y;
    const float* src = z ? Wb : Wa;
    int i = blockIdx.x * 256 + threadIdx.x;
    size_t nl = i >> 8;
    size_t n = z * 16 + nl;
    int j = i & 255, k0 = j * 4;
    uint2 hv = cvt4h(*(const float4*)(src + nl * DIMM + k0));
    pack_store8((char*)g_wab, 32, k0 >> 6, n, (k0 & 63) * 2, hv);
}

// ---------------------------------------------------------------------------
// Big HMMA GEMM, fp16 single-pass, bulk-copy fed.
// CTA 256x128, warp tile 64x64, K chunk 64, 2-stage mbarrier pipeline.
// MODE 0: QKV merged -> SiLU -> g_{q,k,v}lin.   MODE 1: O projection -> Cout.
// ---------------------------------------------------------------------------
template<int MODE>
__global__ __launch_bounds__(256, 1)
void hmma_big(const float* __restrict__ bias_q, const float* __restrict__ bias_k,
              const float* __restrict__ bias_v, float* __restrict__ Cout)
{
    extern __shared__ char smraw[];
    uint32_t base = (smem_u32(smraw) + 1023u) & ~1023u;

    constexpr int ATILE = 256 * 128;   // 32KB
    constexpr int BTILE = 128 * 128;   // 16KB
    constexpr int STG   = ATILE + BTILE;   // 48KB
    const uint32_t mb0 = base + 2 * STG;
    const uint32_t mb1 = base + 2 * STG + 8;

    const char *Ah, *Bh;
    const float* bias;
    float* C;
    int bn_idx;
    if (MODE == 0) {
        const int wsel = blockIdx.x >> 3;
        bn_idx = blockIdx.x & 7;
        Ah = (const char*)g_xh;
        Bh   = (const char*)((wsel == 0) ? g_wq : (wsel == 1) ? g_wk : g_wv);
        bias = (wsel == 0) ? bias_q : (wsel == 1) ? bias_k : bias_v;
        C    = (wsel == 0) ? g_qlin : (wsel == 1) ? g_klin : g_vlin;
    } else {
        bn_idx = blockIdx.x;
        Ah = (const char*)g_oh;
        Bh = (const char*)g_wo;
        bias = bias_q; C = Cout;
    }

    const int tid = threadIdx.x;
    const int wid = tid >> 5;
    const int lid = tid & 31;
    const int bm = blockIdx.y * 256;
    const int bn = bn_idx * 128;

    const int warp_m0 = (wid & 3) * 64;
    const int warp_n0 = (wid >> 2) * 64;
    const int a_row = lid & 15;
    const int a_sel = lid >> 4;
    const int b_row = (lid & 7) + ((lid >> 4) << 3);
    const int b_sel = (lid >> 3) & 1;

    if (tid == 0) { MBAR_INIT(mb0, 1); MBAR_INIT(mb1, 1); }
    __syncthreads();

    if (tid == 0) {
        FENCE_ASYNC();
#pragma unroll
        for (int c = 0; c < 2; c++) {
            uint32_t st = base + c * STG;
            uint32_t mb = c ? mb1 : mb0;
            MBAR_EXPECT(mb, (uint32_t)STG);
            bulk_ld(st,         Ah + ((size_t)c * MM + bm) * 128,   ATILE, mb);
            bulk_ld(st + ATILE, Bh + ((size_t)c * DIMM + bn) * 128, BTILE, mb);
        }
    }

    float acc[4][8][4];
#pragma unroll
    for (int mi = 0; mi < 4; mi++)
#pragma unroll
        for (int ni = 0; ni < 8; ni++)
#pragma unroll
            for (int j = 0; j < 4; j++) acc[mi][ni][j] = 0.f;

    uint32_t ph0 = 0, ph1 = 0;

    for (int c = 0; c < 16; c++) {
        const int s = c & 1;
        const uint32_t st = base + s * STG;
        if (s) { MBAR_WAIT(mb1, ph1); ph1 ^= 1; }
        else   { MBAR_WAIT(mb0, ph0); ph0 ^= 1; }

        const uint32_t sA = st, sB = st + ATILE;

#pragma unroll
        for (int ks = 0; ks < 4; ks++) {
            uint32_t bh[8][2];
#pragma unroll
            for (int j = 0; j < 4; j++) {
                uint32_t off = (uint32_t)(warp_n0 + j * 16 + b_row) * 128 + ks * 32 + b_sel * 16;
                uint32_t t4[4];
                ldsm4(t4, sB + SWZ128(off));
                bh[2*j][0] = t4[0]; bh[2*j][1] = t4[1];
                bh[2*j+1][0] = t4[2]; bh[2*j+1][1] = t4[3];
            }
#pragma unroll
            for (int mi = 0; mi < 4; mi++) {
                uint32_t ah[4];
                uint32_t off = (uint32_t)(warp_m0 + mi * 16 + a_row) * 128 + ks * 32 + a_sel * 16;
                ldsm4(ah, sA + SWZ128(off));
#pragma unroll
                for (int ni = 0; ni < 8; ni++)
                    mma_f16(acc[mi][ni], ah, bh[ni]);
            }
        }
        __syncthreads();

        if (c + 2 < 16 && tid == 0) {
            const int cn = c + 2;
            const uint32_t mb = s ? mb1 : mb0;
            MBAR_EXPECT(mb, (uint32_t)STG);
            bulk_ld(st,         Ah + ((size_t)cn * MM + bm) * 128,   ATILE, mb);
            bulk_ld(st + ATILE, Bh + ((size_t)cn * DIMM + bn) * 128, BTILE, mb);
        }
    }

    // epilogue
#pragma unroll
    for (int mi = 0; mi < 4; mi++) {
        int r0 = bm + warp_m0 + mi * 16 + (lid >> 2);
        int r1 = r0 + 8;
#pragma unroll
        for (int ni = 0; ni < 8; ni++) {
            int col = bn + warp_n0 + ni * 8 + (lid & 3) * 2;
            float bx = __ldg(&bias[col]), by = __ldg(&bias[col + 1]);
            float v0 = acc[mi][ni][0] + bx, v1 = acc[mi][ni][1] + by;
            float v2 = acc[mi][ni][2] + bx, v3 = acc[mi][ni][3] + by;
            if (MODE == 0) { v0 = siluf_(v0); v1 = siluf_(v1); v2 = siluf_(v2); v3 = siluf_(v3); }
            *(float2*)&C[(size_t)r0 * DIMM + col] = make_float2(v0, v1);
            *(float2*)&C[(size_t)r1 * DIMM + col] = make_float2(v2, v3);
        }
    }
}

// ---------------------------------------------------------------------------
// Gate GEMM (N=32), fp16 single-pass, bulk-fed. 8 m-warps, warp tile 16x32.
// ---------------------------------------------------------------------------
__global__ __launch_bounds__(256, 1)
void hmma_gate(const float* __restrict__ ba, const float* __restrict__ bb)
{
    extern __shared__ char smraw[];
    uint32_t base = (smem_u32(smraw) + 1023u) & ~1023u;

    constexpr int ATILE = 128 * 128;  // 16KB
    constexpr int BTILE = 32 * 128;   // 4KB
    constexpr int STG   = ATILE + BTILE;  // 20KB
    const uint32_t mb0 = base + 2 * STG;
    const uint32_t mb1 = base + 2 * STG + 8;

    const int tid = threadIdx.x;
    const int wid = tid >> 5;
    const int lid = tid & 31;
    const int bm = blockIdx.y * 128;

    const int warp_m0 = wid * 16;
    const int a_row = lid & 15;
    const int a_sel = lid >> 4;
    const int b_row = (lid & 7) + ((lid >> 4) << 3);
    const int b_sel = (lid >> 3) & 1;

    if (tid == 0) { MBAR_INIT(mb0, 1); MBAR_INIT(mb1, 1); }
    __syncthreads();

    if (tid == 0) {
        FENCE_ASYNC();
#pragma unroll
        for (int c = 0; c < 2; c++) {
            uint32_t st = base + c * STG;
            uint32_t mb = c ? mb1 : mb0;
            MBAR_EXPECT(mb, (uint32_t)STG);
            bulk_ld(st,         (const char*)g_xh  + ((size_t)c * MM + bm) * 128, ATILE, mb);
            bulk_ld(st + ATILE, (const char*)g_wab + (size_t)c * 32 * 128,        BTILE, mb);
        }
    }

    float acc[4][4];
#pragma unroll
    for (int ni = 0; ni < 4; ni++)
#pragma unroll
        for (int j = 0; j < 4; j++) acc[ni][j] = 0.f;

    uint32_t ph0 = 0, ph1 = 0;

    for (int c = 0; c < 16; c++) {
        const int s = c & 1;
        const uint32_t st = base + s * STG;
        if (s) { MBAR_WAIT(mb1, ph1); ph1 ^= 1; }
        else   { MBAR_WAIT(mb0, ph0); ph0 ^= 1; }

        const uint32_t sA = st, sB = st + ATILE;

#pragma unroll
        for (int ks = 0; ks < 4; ks++) {
            uint32_t ah[4];
            {
                uint32_t off = (uint32_t)(warp_m0 + a_row) * 128 + ks * 32 + a_sel * 16;
                ldsm4(ah, sA + SWZ128(off));
            }
            uint32_t bh[4][2];
#pragma unroll
            for (int j = 0; j < 2; j++) {
                uint32_t off = (uint32_t)(j * 16 + b_row) * 128 + ks * 32 + b_sel * 16;
                uint32_t t4[4];
                ldsm4(t4, sB + SWZ128(off));
                bh[2*j][0] = t4[0]; bh[2*j][1] = t4[1];
                bh[2*j+1][0] = t4[2]; bh[2*j+1][1] = t4[3];
            }
#pragma unroll
            for (int ni = 0; ni < 4; ni++)
                mma_f16(acc[ni], ah, bh[ni]);
        }
        __syncthreads();

        if (c + 2 < 16 && tid == 0) {
            const int cn = c + 2;
            const uint32_t mb = s ? mb1 : mb0;
            MBAR_EXPECT(mb, (uint32_t)STG);
            bulk_ld(st,         (const char*)g_xh  + ((size_t)cn * MM + bm) * 128, ATILE, mb);
            bulk_ld(st + ATILE, (const char*)g_wab + (size_t)cn * 32 * 128,        BTILE, mb);
        }
    }

    const int r0 = bm + warp_m0 + (lid >> 2);
#pragma unroll
    for (int ni = 0; ni < 4; ni++) {
        int col = ni * 8 + (lid & 3) * 2;
        float bx = (col < 16) ? __ldg(&ba[col])     : __ldg(&bb[col - 16]);
        float by = (col < 16) ? __ldg(&ba[col + 1]) : __ldg(&bb[col - 15]);
        float* dst = (col < 16) ? g_a : g_bg;
        int cc = (col < 16) ? col : col - 16;
        float2 v0 = { sigmoidf_(acc[ni][0] + bx), sigmoidf_(acc[ni][1] + by) };
        float2 v1 = { sigmoidf_(acc[ni][2] + bx), sigmoidf_(acc[ni][3] + by) };
        *(float2*)&dst[(size_t)r0 * HH + cc] = v0;
        *(float2*)&dst[(size_t)(r0 + 8) * HH + cc] = v1;
    }
}

// ---------------------------------------------------------------------------
// Depthwise conv (K=4, pad=2, truncated) + SiLU + optional L2 norm
// ---------------------------------------------------------------------------
__global__ __launch_bounds__(256)
void conv_norm_kernel(const float* __restrict__ wq, const float* __restrict__ wk,
                      const float* __restrict__ wv)
{
    const int z = blockIdx.y;
    const float* __restrict__ in  = (z == 0) ? g_qlin : (z == 1) ? g_klin : g_vlin;
    const float* __restrict__ w   = (z == 0) ? wq     : (z == 1) ? wk     : wv;
    float* __restrict__ out       = (z == 0) ? g_q    : (z == 1) ? g_k    : g_v;

    const int bt = blockIdx.x;
    const int b = bt / NN;
    const int t = bt % NN;
    const int tid = threadIdx.x;
    const int c0 = tid * 4;

    float4 w0 = *(const float4*)(w + c0 * 4 + 0);
    float4 w1 = *(const float4*)(w + c0 * 4 + 4);
    float4 w2 = *(const float4*)(w + c0 * 4 + 8);
    float4 w3 = *(const float4*)(w + c0 * 4 + 12);
    float wc[4][4] = {{w0.x,w0.y,w0.z,w0.w},{w1.x,w1.y,w1.z,w1.w},
                      {w2.x,w2.y,w2.z,w2.w},{w3.x,w3.y,w3.z,w3.w}};

    float y[4] = {0.f, 0.f, 0.f, 0.f};
#pragma unroll
    for (int j = 0; j < 4; j++) {
        int tt = t + j - 2;
        if (tt >= 0 && tt < NN) {
            float4 xv = *(const float4*)(in + ((size_t)b * NN + tt) * DIMM + c0);
            y[0] += xv.x * wc[0][j];
            y[1] += xv.y * wc[1][j];
            y[2] += xv.z * wc[2][j];
            y[3] += xv.w * wc[3][j];
        }
    }
#pragma unroll
    for (int m = 0; m < 4; m++) y[m] = siluf_(y[m]);

    float ss = y[0]*y[0] + y[1]*y[1] + y[2]*y[2] + y[3]*y[3];
#pragma unroll
    for (int off = 16; off; off >>= 1) ss += __shfl_down_sync(0xffffffffu, ss, off);
    __shared__ float wss[8];
    __shared__ float inv_sh;
    const int lane = tid & 31, widx = tid >> 5;
    if (lane == 0) wss[widx] = ss;
    __syncthreads();
    if (tid == 0) {
        float tot = 0.f;
#pragma unroll
        for (int i = 0; i < 8; i++) tot += wss[i];
        inv_sh = 1.f / (sqrtf(tot) + EPSF);
    }
    __syncthreads();
    float inv = (z < 2) ? inv_sh : 1.f;

    float4 ov; ov.x = y[0]*inv; ov.y = y[1]*inv; ov.z = y[2]*inv; ov.w = y[3]*inv;
    *(float4*)(out + ((size_t)b * NN + t) * DIMM + c0) = ov;
}

// ---------------------------------------------------------------------------
// Gated delta-rule scan, dual-state (S + S^T), f32x2 packed math.
// 128 threads per (b,h).  Group0 (0..63): S rows.  Group1 (64..127): S^T rows,
// write O as packed fp16.
// ---------------------------------------------------------------------------
__global__ __launch_bounds__(128)
void scan_kernel()
{
    const int bh = blockIdx.x;
    const int b = bh >> 4;
    const int h = bh & 15;
    const int tid = threadIdx.x;

    __shared__ __align__(16) float k_sh[2][64];
    __shared__ __align__(16) float q_sh[2][64];
    __shared__ __align__(16) float coef_sh[64];

    const size_t gb = ((size_t)b * NN) * HH + h;

    if (tid < 64) {
        const int d = tid;
        const size_t base = ((size_t)b * NN) * DIMM + h * DHH + d;
        ull_t S2[32];
#pragma unroll
        for (int i = 0; i < 32; i++) S2[i] = 0ull;
        float vc = g_v[base], ac = g_a[gb], bc = g_bg[gb];
        __syncthreads();

        for (int t = 0; t < NN; t++) {
            const ulonglong2* kp = (const ulonglong2*)k_sh[t & 1];
            ull_t kr[32];
#pragma unroll
            for (int i = 0; i < 16; i++) {
                ulonglong2 kk = kp[i];
                kr[2*i] = kk.x; kr[2*i+1] = kk.y;
            }
            ull_t a0 = 0ull, a1 = 0ull, a2 = 0ull, a3 = 0ull;
#pragma unroll
            for (int i = 0; i < 8; i++) {
                FMA2(a0, S2[4*i+0], kr[4*i+0], a0);
                FMA2(a1, S2[4*i+1], kr[4*i+1], a1);
                FMA2(a2, S2[4*i+2], kr[4*i+2], a2);
                FMA2(a3, S2[4*i+3], kr[4*i+3], a3);
            }
            float x0, y0, x1, y1, x2, y2, x3, y3;
            unpack2(a0, x0, y0); unpack2(a1, x1, y1);
            unpack2(a2, x2, y2); unpack2(a3, x3, y3);
            float sk = ((x0 + y0) + (x1 + y1)) + ((x2 + y2) + (x3 + y3));
            float coef = bc * vc - ac * bc * sk;
            coef_sh[d] = coef;
            float vn = 0.f, an = 0.f, bn = 0.f;
            if (t + 1 < NN) {
                vn = g_v[base + (size_t)(t + 1) * DIMM];
                an = g_a[gb + (size_t)(t + 1) * HH];
                bn = g_bg[gb + (size_t)(t + 1) * HH];
            }
            __syncthreads();   // bar A: coef visible to group1
            ull_t av2 = pack2(ac, ac), cf2 = pack2(coef, coef);
#pragma unroll
            for (int i = 0; i < 32; i++) {
                ull_t tmp;
                MUL2(tmp, av2, S2[i]);
                FMA2(S2[i], cf2, kr[i], tmp);
            }
            vc = vn; ac = an; bc = bn;
            __syncthreads();   // bar B
        }
    } else {
        const int e = tid - 64;
        const size_t base = ((size_t)b * NN) * DIMM + h * DHH + e;
        ull_t T2[32];
#pragma unroll
        for (int i = 0; i < 32; i++) T2[i] = 0ull;
        float kc = g_k[base];
        float qc = g_q[base];
        k_sh[0][e] = kc;
        q_sh[0][e] = qc;
        float ac = g_a[gb];
        float kn = 0.f, qn = 0.f;
        if (NN > 1) { kn = g_k[base + DIMM]; qn = g_q[base + DIMM]; }
        __syncthreads();

        for (int t = 0; t < NN; t++) {
            const int buf = t & 1;
            float an = 0.f, kn2 = 0.f, qn2 = 0.f;
            if (t + 1 < NN) an = g_a[gb + (size_t)(t + 1) * HH];
            if (t + 2 < NN) {
                kn2 = g_k[base + (size_t)(t + 2) * DIMM];
                qn2 = g_q[base + (size_t)(t + 2) * DIMM];
            }
            __syncthreads();   // bar A: coef ready
            ull_t av2 = pack2(ac, ac), kc2 = pack2(kc, kc);
            const ulonglong2* cfp = (const ulonglong2*)coef_sh;
            const ulonglong2* qp  = (const ulonglong2*)q_sh[buf];
            ull_t o0 = 0ull, o1 = 0ull, o2 = 0ull, o3 = 0ull;
#pragma unroll
            for (int i = 0; i < 16; i++) {
                ulonglong2 cf = cfp[i];
                ulonglong2 qv = qp[i];
                ull_t t0, t1, u0, u1;
                MUL2(t0, cf.x, kc2);
                FMA2(u0, av2, T2[2*i],   t0); T2[2*i]   = u0;
                MUL2(t1, cf.y, kc2);
                FMA2(u1, av2, T2[2*i+1], t1); T2[2*i+1] = u1;
                if (i & 1) { FMA2(o1, u0, qv.x, o1); FMA2(o3, u1, qv.y, o3); }
                else       { FMA2(o0, u0, qv.x, o0); FMA2(o2, u1, qv.y, o2); }
            }
            float x0, y0, x1, y1, x2, y2, x3, y3;
            unpack2(o0, x0, y0); unpack2(o1, x1, y1);
            unpack2(o2, x2, y2); unpack2(o3, x3, y3);
            float o = (((x0 + y0) + (x1 + y1)) + ((x2 + y2) + (x3 + y3)));
            // packed fp16 write: chunk = h, row m = b*NN+t, inner byte = e*2
            size_t m = (size_t)b * NN + t;
            size_t off = ((size_t)h * MM + m) * 128 + (size_t)((e * 2) ^ (((int)m & 7) << 4));
            *(__half*)((char*)g_oh + off) = __float2half_rn(o);
            if (t + 1 < NN) {
                k_sh[buf ^ 1][e] = kn;
                q_sh[buf ^ 1][e] = qn;
            }
            kc = kn; kn = kn2; qn = qn2; ac = an;
            __syncthreads();   // bar B
        }
    }
}

// ---------------------------------------------------------------------------
// Launch (ncu profiles my launch index 3 -> QKV GEMM there)
// ---------------------------------------------------------------------------
extern "C" void kernel_launch(void* const* d_in, const int* in_sizes, int n_in,
                              void* d_out, int out_size)
{
    (void)in_sizes; (void)n_in; (void)out_size;
    const float* x      = (const float*)d_in[0];
    const float* Wq     = (const float*)d_in[1];
    const float* bq     = (const float*)d_in[2];
    const float* Wk     = (const float*)d_in[3];
    const float* bk     = (const float*)d_in[4];
    const float* Wv     = (const float*)d_in[5];
    const float* bv     = (const float*)d_in[6];
    const float* Wa     = (const float*)d_in[7];
    const float* ba     = (const float*)d_in[8];
    const float* Wb     = (const float*)d_in[9];
    const float* bb     = (const float*)d_in[10];
    const float* conv_q = (const float*)d_in[11];
    const float* conv_k = (const float*)d_in[12];
    const float* conv_v = (const float*)d_in[13];
    const float* Wo     = (const float*)d_in[14];
    const float* bo     = (const float*)d_in[15];
    float* out = (float*)d_out;

    const int smem_big  = 1024 + 2 * (256 * 128 + 128 * 128) + 64;  // ~99KB
    const int smem_gate = 1024 + 2 * (128 * 128 + 32 * 128) + 64;   // ~42KB
    cudaFuncSetAttribute(hmma_big<0>, cudaFuncAttributeMaxDynamicSharedMemorySize, smem_big);
    cudaFuncSetAttribute(hmma_big<1>, cudaFuncAttributeMaxDynamicSharedMemorySize, smem_big);
    cudaFuncSetAttribute(hmma_gate,   cudaFuncAttributeMaxDynamicSharedMemorySize, smem_gate);

    // [0],[1]: x pack halves
    cvt_x_pack<<<MM / 2, 256>>>(x, 0);
    cvt_x_pack<<<MM / 2, 256>>>(x, MM / 2);
    // [2]: big weights pack
    cvt_w_pack<<<dim3(DIMM, 4), 256>>>(Wq, Wk, Wv, Wo);
    // [3]: merged QKV GEMM  <-- ncu capture
    hmma_big<0><<<dim3(24, 64), 256, smem_big>>>(bq, bk, bv, nullptr);
    // [4]: gate weights pack
    cvt_ab_pack<<<dim3(16, 2), 256>>>(Wa, Wb);
    // [5]: gates
    hmma_gate<<<dim3(1, 128), 256, smem_gate>>>(ba, bb);
    // [6]: conv + norm
    conv_norm_kernel<<<dim3(MM, 3), 256>>>(conv_q, conv_k, conv_v);
    // [7]: scan
    scan_kernel<<<BB * HH, 128>>>();
    // [8]: output projection
    hmma_big<1><<<dim3(8, 64), 256, smem_big>>>(bo, nullptr, nullptr, out);
}

// round 10
// speedup vs baseline: 4.7908x; 1.7998x over previous
#include <cuda_runtime.h>
#include <cuda_fp16.h>
#include <cstdint>

// Problem constants
#define BB   8
#define NN   2048
#define DIMM 1024
#define HH   16
#define DHH  64
#define MM   (BB*NN)          // 16384 rows
#define EPSF 1e-6f

typedef unsigned long long ull_t;

// ---------------------------------------------------------------------------
// Scratch (device globals; no allocation allowed)
// ---------------------------------------------------------------------------
__device__ float g_qlin[BB*NN*DIMM];
__device__ float g_klin[BB*NN*DIMM];
__device__ float g_vlin[BB*NN*DIMM];
// head-major scan inputs: [bh][t][64]
__device__ float g_qs[BB*HH*NN*DHH];
__device__ float g_ks[BB*HH*NN*DHH];
__device__ float g_vs[BB*HH*NN*DHH];
// head-major gates: [bh][t]
__device__ float g_as[BB*HH*NN];
__device__ float g_bs[BB*HH*NN];

// chunk-packed, pre-swizzled fp16 operands: [c][row][128B], inner byte xor
// (ib ^ ((row&7)<<4)) baked in.
__device__ __half g_xh[MM*DIMM];
__device__ __half g_oh[MM*DIMM];
__device__ __half g_wq[DIMM*DIMM];
__device__ __half g_wk[DIMM*DIMM];
__device__ __half g_wv[DIMM*DIMM];
__device__ __half g_wo[DIMM*DIMM];
__device__ __half g_wab[32*DIMM];

__device__ __forceinline__ float sigmoidf_(float x) { return 1.f / (1.f + __expf(-x)); }
__device__ __forceinline__ float siluf_(float x)    { return x / (1.f + __expf(-x)); }

// ---------------------------------------------------------------------------
// PTX helpers
// ---------------------------------------------------------------------------
__device__ __forceinline__ uint32_t smem_u32(const void* p) {
    uint32_t a;
    asm("{ .reg .u64 t; cvta.to.shared.u64 t, %1; cvt.u32.u64 %0, t; }" : "=r"(a) : "l"(p));
    return a;
}
#define SWZ128(o) ((o) ^ (((o) >> 3) & 0x70))

__device__ __forceinline__ void ldsm4(uint32_t* r, uint32_t addr) {
    asm volatile("ldmatrix.sync.aligned.m8n8.x4.shared.b16 {%0,%1,%2,%3}, [%4];"
                 : "=r"(r[0]), "=r"(r[1]), "=r"(r[2]), "=r"(r[3]) : "r"(addr));
}
__device__ __forceinline__ void mma_f16(float* d, const uint32_t* a, const uint32_t* b) {
    asm volatile(
        "mma.sync.aligned.m16n8k16.row.col.f32.f16.f16.f32 "
        "{%0,%1,%2,%3}, {%4,%5,%6,%7}, {%8,%9}, {%0,%1,%2,%3};"
        : "+f"(d[0]), "+f"(d[1]), "+f"(d[2]), "+f"(d[3])
        : "r"(a[0]), "r"(a[1]), "r"(a[2]), "r"(a[3]), "r"(b[0]), "r"(b[1]));
}

__device__ __forceinline__ void bulk_ld(uint32_t dst, const void* src, uint32_t bytes,
                                        uint32_t mbar) {
    asm volatile(
        "cp.async.bulk.shared::cluster.global.mbarrier::complete_tx::bytes [%0], [%1], %2, [%3];"
        :: "r"(dst), "l"(src), "r"(bytes), "r"(mbar) : "memory");
}
#define MBAR_INIT(a, c)   asm volatile("mbarrier.init.shared.b64 [%0], %1;" :: "r"(a), "r"(c) : "memory")
#define MBAR_EXPECT(a, n) asm volatile("mbarrier.arrive.expect_tx.shared.b64 _, [%0], %1;" :: "r"(a), "r"(n) : "memory")
#define FENCE_ASYNC()     asm volatile("fence.proxy.async.shared::cta;" ::: "memory")
#define MBAR_WAIT(a, ph) do {                                                   \
    uint32_t _m = (a), _p = (ph), _d;                                           \
    asm volatile("{\n\t.reg .pred p;\n\t"                                       \
        "mbarrier.try_wait.parity.acquire.cta.shared::cta.b64 p, [%1], %2;\n\t" \
        "selp.b32 %0, 1, 0, p;\n\t}" : "=r"(_d) : "r"(_m), "r"(_p) : "memory"); \
    if (!_d) {                                                                  \
        asm volatile("{\n\t.reg .pred P1;\n\tWL_%=: \n\t"                       \
            "mbarrier.try_wait.parity.acquire.cta.shared::cta.b64 P1, [%0], %1, 0x989680;\n\t" \
            "@P1 bra.uni WD_%=;\n\tbra.uni WL_%=;\n\tWD_%=:\n\t}"               \
            :: "r"(_m), "r"(_p) : "memory");                                    \
    }                                                                           \
} while (0)

// packed f32x2 (PTX 8.6, sm_100+ family)
#define FMA2(d, a, b, c) asm("fma.rn.f32x2 %0, %1, %2, %3;" : "=l"(d) : "l"(a), "l"(b), "l"(c))
#define MUL2(d, a, b)    asm("mul.rn.f32x2 %0, %1, %2;"     : "=l"(d) : "l"(a), "l"(b))
__device__ __forceinline__ ull_t pack2(float x, float y) {
    ull_t r; asm("mov.b64 %0, {%1, %2};" : "=l"(r) : "f"(x), "f"(y)); return r;
}
__device__ __forceinline__ void unpack2(ull_t v, float& x, float& y) {
    asm("mov.b64 {%0, %1}, %2;" : "=f"(x), "=f"(y) : "l"(v));
}

// ---------------------------------------------------------------------------
// fp16 pack conversions.  Packed byte address for (chunk, row, inner byte ib):
//   ((chunk*rows + row)*128) + (ib ^ ((row&7)<<4))
// ---------------------------------------------------------------------------
__device__ __forceinline__ uint2 cvt4h(const float4 v) {
    uint2 r;
    r.x = (uint32_t)__half_as_ushort(__float2half_rn(v.x))
        | ((uint32_t)__half_as_ushort(__float2half_rn(v.y)) << 16);
    r.y = (uint32_t)__half_as_ushort(__float2half_rn(v.z))
        | ((uint32_t)__half_as_ushort(__float2half_rn(v.w)) << 16);
    return r;
}
__device__ __forceinline__ void pack_store8(char* basep, size_t rows, int chunk,
                                            size_t row, int ib, uint2 v) {
    size_t off = ((size_t)chunk * rows + row) * 128 + (size_t)(ib ^ (((int)row & 7) << 4));
    *(uint2*)(basep + off) = v;
}

__global__ __launch_bounds__(256)
void cvt_x_pack(const float* __restrict__ x)
{
    int i = blockIdx.x * 256 + threadIdx.x;
    size_t m = i >> 8;
    int j = i & 255, k0 = j * 4;
    uint2 hv = cvt4h(*(const float4*)(x + m * DIMM + k0));
    pack_store8((char*)g_xh, MM, k0 >> 6, m, (k0 & 63) * 2, hv);
}

__global__ __launch_bounds__(256)
void cvt_w_pack(const float* __restrict__ Wq, const float* __restrict__ Wk,
                const float* __restrict__ Wv, const float* __restrict__ Wo)
{
    const int z = blockIdx.y;
    const float* src = (z == 0) ? Wq : (z == 1) ? Wk : (z == 2) ? Wv : Wo;
    char* dst = (char*)((z == 0) ? g_wq : (z == 1) ? g_wk : (z == 2) ? g_wv : g_wo);
    int i = blockIdx.x * 256 + threadIdx.x;
    size_t n = i >> 8;
    int j = i & 255, k0 = j * 4;
    uint2 hv = cvt4h(*(const float4*)(src + n * DIMM + k0));
    pack_store8(dst, DIMM, k0 >> 6, n, (k0 & 63) * 2, hv);
}

__global__ __launch_bounds__(256)
void cvt_ab_pack(const float* __restrict__ Wa, const float* __restrict__ Wb)
{
    const int z = blockIdx.y;
    const float* src = z ? Wb : Wa;
    int i = blockIdx.x * 256 + threadIdx.x;
    size_t nl = i >> 8;
    size_t n = z * 16 + nl;
    int j = i & 255, k0 = j * 4;
    uint2 hv = cvt4h(*(const float4*)(src + nl * DIMM + k0));
    pack_store8((char*)g_wab, 32, k0 >> 6, n, (k0 & 63) * 2, hv);
}

// ---------------------------------------------------------------------------
// Big HMMA GEMM, fp16 single-pass, bulk-fed, 3-stage pipeline.
// CTA 256x128, warp tile 64x64, K chunk 64.
// MODE 0: QKV merged -> SiLU -> g_{q,k,v}lin.   MODE 1: O projection -> Cout.
// ---------------------------------------------------------------------------
template<int MODE>
__global__ __launch_bounds__(256, 1)
void hmma_big(const float* __restrict__ bias_q, const float* __restrict__ bias_k,
              const float* __restrict__ bias_v, float* __restrict__ Cout)
{
    extern __shared__ char smraw[];
    uint32_t base = (smem_u32(smraw) + 1023u) & ~1023u;

    constexpr int ATILE = 256 * 128;   // 32KB
    constexpr int BTILE = 128 * 128;   // 16KB
    constexpr int STG   = ATILE + BTILE;   // 48KB
    const uint32_t mbb = base + 3 * STG;   // 3 mbarriers

    const char *Ah, *Bh;
    const float* bias;
    float* C;
    int bn_idx;
    if (MODE == 0) {
        const int wsel = blockIdx.x >> 3;
        bn_idx = blockIdx.x & 7;
        Ah = (const char*)g_xh;
        Bh   = (const char*)((wsel == 0) ? g_wq : (wsel == 1) ? g_wk : g_wv);
        bias = (wsel == 0) ? bias_q : (wsel == 1) ? bias_k : bias_v;
        C    = (wsel == 0) ? g_qlin : (wsel == 1) ? g_klin : g_vlin;
    } else {
        bn_idx = blockIdx.x;
        Ah = (const char*)g_oh;
        Bh = (const char*)g_wo;
        bias = bias_q; C = Cout;
    }

    const int tid = threadIdx.x;
    const int wid = tid >> 5;
    const int lid = tid & 31;
    const int bm = blockIdx.y * 256;
    const int bn = bn_idx * 128;

    const int warp_m0 = (wid & 3) * 64;
    const int warp_n0 = (wid >> 2) * 64;
    const int a_row = lid & 15;
    const int a_sel = lid >> 4;
    const int b_row = (lid & 7) + ((lid >> 4) << 3);
    const int b_sel = (lid >> 3) & 1;

    if (tid == 0) {
        MBAR_INIT(mbb, 1); MBAR_INIT(mbb + 8, 1); MBAR_INIT(mbb + 16, 1);
    }
    __syncthreads();

    if (tid == 0) {
        FENCE_ASYNC();
#pragma unroll
        for (int c = 0; c < 3; c++) {
            uint32_t st = base + c * STG;
            uint32_t mb = mbb + c * 8;
            MBAR_EXPECT(mb, (uint32_t)STG);
            bulk_ld(st,         Ah + ((size_t)c * MM + bm) * 128,   ATILE, mb);
            bulk_ld(st + ATILE, Bh + ((size_t)c * DIMM + bn) * 128, BTILE, mb);
        }
    }

    float acc[4][8][4];
#pragma unroll
    for (int mi = 0; mi < 4; mi++)
#pragma unroll
        for (int ni = 0; ni < 8; ni++)
#pragma unroll
            for (int j = 0; j < 4; j++) acc[mi][ni][j] = 0.f;

    for (int c = 0; c < 16; c++) {
        const int s = c % 3;
        const uint32_t st = base + s * STG;
        MBAR_WAIT(mbb + s * 8, (c / 3) & 1);

        const uint32_t sA = st, sB = st + ATILE;

#pragma unroll
        for (int ks = 0; ks < 4; ks++) {
            uint32_t bh[8][2];
#pragma unroll
            for (int j = 0; j < 4; j++) {
                uint32_t off = (uint32_t)(warp_n0 + j * 16 + b_row) * 128 + ks * 32 + b_sel * 16;
                uint32_t t4[4];
                ldsm4(t4, sB + SWZ128(off));
                bh[2*j][0] = t4[0]; bh[2*j][1] = t4[1];
                bh[2*j+1][0] = t4[2]; bh[2*j+1][1] = t4[3];
            }
#pragma unroll
            for (int mi = 0; mi < 4; mi++) {
                uint32_t ah[4];
                uint32_t off = (uint32_t)(warp_m0 + mi * 16 + a_row) * 128 + ks * 32 + a_sel * 16;
                ldsm4(ah, sA + SWZ128(off));
#pragma unroll
                for (int ni = 0; ni < 8; ni++)
                    mma_f16(acc[mi][ni], ah, bh[ni]);
            }
        }
        __syncthreads();

        if (c + 3 < 16 && tid == 0) {
            const int cn = c + 3;
            const uint32_t mb = mbb + s * 8;
            FENCE_ASYNC();
            MBAR_EXPECT(mb, (uint32_t)STG);
            bulk_ld(st,         Ah + ((size_t)cn * MM + bm) * 128,   ATILE, mb);
            bulk_ld(st + ATILE, Bh + ((size_t)cn * DIMM + bn) * 128, BTILE, mb);
        }
    }

    // epilogue
#pragma unroll
    for (int mi = 0; mi < 4; mi++) {
        int r0 = bm + warp_m0 + mi * 16 + (lid >> 2);
        int r1 = r0 + 8;
#pragma unroll
        for (int ni = 0; ni < 8; ni++) {
            int col = bn + warp_n0 + ni * 8 + (lid & 3) * 2;
            float bx = __ldg(&bias[col]), by = __ldg(&bias[col + 1]);
            float v0 = acc[mi][ni][0] + bx, v1 = acc[mi][ni][1] + by;
            float v2 = acc[mi][ni][2] + bx, v3 = acc[mi][ni][3] + by;
            if (MODE == 0) { v0 = siluf_(v0); v1 = siluf_(v1); v2 = siluf_(v2); v3 = siluf_(v3); }
            *(float2*)&C[(size_t)r0 * DIMM + col] = make_float2(v0, v1);
            *(float2*)&C[(size_t)r1 * DIMM + col] = make_float2(v2, v3);
        }
    }
}

// ---------------------------------------------------------------------------
// Gate GEMM (N=32), fp16, bulk-fed, 2-stage. Writes head-major g_as/g_bs.
// ---------------------------------------------------------------------------
__global__ __launch_bounds__(256, 1)
void hmma_gate(const float* __restrict__ ba, const float* __restrict__ bb)
{
    extern __shared__ char smraw[];
    uint32_t base = (smem_u32(smraw) + 1023u) & ~1023u;

    constexpr int ATILE = 128 * 128;  // 16KB
    constexpr int BTILE = 32 * 128;   // 4KB
    constexpr int STG   = ATILE + BTILE;  // 20KB
    const uint32_t mb0 = base + 2 * STG;
    const uint32_t mb1 = base + 2 * STG + 8;

    const int tid = threadIdx.x;
    const int wid = tid >> 5;
    const int lid = tid & 31;
    const int bm = blockIdx.y * 128;

    const int warp_m0 = wid * 16;
    const int a_row = lid & 15;
    const int a_sel = lid >> 4;
    const int b_row = (lid & 7) + ((lid >> 4) << 3);
    const int b_sel = (lid >> 3) & 1;

    if (tid == 0) { MBAR_INIT(mb0, 1); MBAR_INIT(mb1, 1); }
    __syncthreads();

    if (tid == 0) {
        FENCE_ASYNC();
#pragma unroll
        for (int c = 0; c < 2; c++) {
            uint32_t st = base + c * STG;
            uint32_t mb = c ? mb1 : mb0;
            MBAR_EXPECT(mb, (uint32_t)STG);
            bulk_ld(st,         (const char*)g_xh  + ((size_t)c * MM + bm) * 128, ATILE, mb);
            bulk_ld(st + ATILE, (const char*)g_wab + (size_t)c * 32 * 128,        BTILE, mb);
        }
    }

    float acc[4][4];
#pragma unroll
    for (int ni = 0; ni < 4; ni++)
#pragma unroll
        for (int j = 0; j < 4; j++) acc[ni][j] = 0.f;

    uint32_t ph0 = 0, ph1 = 0;

    for (int c = 0; c < 16; c++) {
        const int s = c & 1;
        const uint32_t st = base + s * STG;
        if (s) { MBAR_WAIT(mb1, ph1); ph1 ^= 1; }
        else   { MBAR_WAIT(mb0, ph0); ph0 ^= 1; }

        const uint32_t sA = st, sB = st + ATILE;

#pragma unroll
        for (int ks = 0; ks < 4; ks++) {
            uint32_t ah[4];
            {
                uint32_t off = (uint32_t)(warp_m0 + a_row) * 128 + ks * 32 + a_sel * 16;
                ldsm4(ah, sA + SWZ128(off));
            }
            uint32_t bh[4][2];
#pragma unroll
            for (int j = 0; j < 2; j++) {
                uint32_t off = (uint32_t)(j * 16 + b_row) * 128 + ks * 32 + b_sel * 16;
                uint32_t t4[4];
                ldsm4(t4, sB + SWZ128(off));
                bh[2*j][0] = t4[0]; bh[2*j][1] = t4[1];
                bh[2*j+1][0] = t4[2]; bh[2*j+1][1] = t4[3];
            }
#pragma unroll
            for (int ni = 0; ni < 4; ni++)
                mma_f16(acc[ni], ah, bh[ni]);
        }
        __syncthreads();

        if (c + 2 < 16 && tid == 0) {
            const int cn = c + 2;
            const uint32_t mb = s ? mb1 : mb0;
            FENCE_ASYNC();
            MBAR_EXPECT(mb, (uint32_t)STG);
            bulk_ld(st,         (const char*)g_xh  + ((size_t)cn * MM + bm) * 128, ATILE, mb);
            bulk_ld(st + ATILE, (const char*)g_wab + (size_t)cn * 32 * 128,        BTILE, mb);
        }
    }

    // epilogue: head-major stores  a/b[(b*HH+h)*NN + t]
#pragma unroll
    for (int rr = 0; rr < 2; rr++) {
        int r = bm + warp_m0 + (lid >> 2) + rr * 8;
        int b0 = r >> 11, t0 = r & 2047;
#pragma unroll
        for (int ni = 0; ni < 4; ni++) {
            int col = ni * 8 + (lid & 3) * 2;
            float a0 = acc[ni][rr * 2 + 0], a1 = acc[ni][rr * 2 + 1];
            float bx = (col < 16) ? __ldg(&ba[col])     : __ldg(&bb[col - 16]);
            float by = (col < 16) ? __ldg(&ba[col + 1]) : __ldg(&bb[col - 15]);
            float* dst = (col < 16) ? g_as : g_bs;
            int cc = (col < 16) ? col : col - 16;
            dst[((size_t)b0 * HH + cc)     * NN + t0] = sigmoidf_(a0 + bx);
            dst[((size_t)b0 * HH + cc + 1) * NN + t0] = sigmoidf_(a1 + by);
        }
    }
}

// ---------------------------------------------------------------------------
// Depthwise conv (K=4, pad=2) + SiLU + optional L2 norm (over full 1024 dim).
// 4 outputs (t) per thread; writes head-major [bh][t][64].
// grid (MM/4, 3), 256 threads.
// ---------------------------------------------------------------------------
__global__ __launch_bounds__(256)
void conv_norm_kernel(const float* __restrict__ wq, const float* __restrict__ wk,
                      const float* __restrict__ wv)
{
    const int z = blockIdx.y;
    const float* __restrict__ in  = (z == 0) ? g_qlin : (z == 1) ? g_klin : g_vlin;
    const float* __restrict__ w   = (z == 0) ? wq     : (z == 1) ? wk     : wv;
    float* __restrict__ out       = (z == 0) ? g_qs   : (z == 1) ? g_ks   : g_vs;

    const int bt4 = blockIdx.x;          // 0 .. MM/4-1
    const int b   = bt4 >> 9;            // NN/4 = 512 groups per b
    const int t0  = (bt4 & 511) * 4;
    const int tid = threadIdx.x;
    const int c0 = tid * 4;
    const int h  = c0 >> 6;
    const int d0 = c0 & 63;

    float4 w0 = *(const float4*)(w + c0 * 4 + 0);
    float4 w1 = *(const float4*)(w + c0 * 4 + 4);
    float4 w2 = *(const float4*)(w + c0 * 4 + 8);
    float4 w3 = *(const float4*)(w + c0 * 4 + 12);
    float wc[4][4] = {{w0.x,w0.y,w0.z,w0.w},{w1.x,w1.y,w1.z,w1.w},
                      {w2.x,w2.y,w2.z,w2.w},{w3.x,w3.y,w3.z,w3.w}};

    // rows t0-2 .. t0+4
    float xr[7][4];
#pragma unroll
    for (int i = 0; i < 7; i++) {
        int r = t0 - 2 + i;
        if (r >= 0 && r < NN) {
            float4 xv = *(const float4*)(in + ((size_t)b * NN + r) * DIMM + c0);
            xr[i][0] = xv.x; xr[i][1] = xv.y; xr[i][2] = xv.z; xr[i][3] = xv.w;
        } else {
            xr[i][0] = xr[i][1] = xr[i][2] = xr[i][3] = 0.f;
        }
    }

    float y[4][4];
    float ss[4];
#pragma unroll
    for (int ot = 0; ot < 4; ot++) {
        ss[ot] = 0.f;
#pragma unroll
        for (int m = 0; m < 4; m++) {
            float acc = 0.f;
#pragma unroll
            for (int j = 0; j < 4; j++)
                acc += xr[ot + j][m] * wc[m][j];
            acc = siluf_(acc);
            y[ot][m] = acc;
            ss[ot] += acc * acc;
        }
    }

    // block-wide reduction of 4 sums (one per output t)
#pragma unroll
    for (int off = 16; off; off >>= 1) {
#pragma unroll
        for (int ot = 0; ot < 4; ot++)
            ss[ot] += __shfl_down_sync(0xffffffffu, ss[ot], off);
    }
    __shared__ float4 wss[8];
    __shared__ float4 inv_sh;
    const int lane = tid & 31, widx = tid >> 5;
    if (lane == 0) wss[widx] = make_float4(ss[0], ss[1], ss[2], ss[3]);
    __syncthreads();
    if (tid == 0) {
        float4 tot = make_float4(0.f, 0.f, 0.f, 0.f);
#pragma unroll
        for (int i = 0; i < 8; i++) {
            tot.x += wss[i].x; tot.y += wss[i].y;
            tot.z += wss[i].z; tot.w += wss[i].w;
        }
        inv_sh = make_float4(1.f / (sqrtf(tot.x) + EPSF), 1.f / (sqrtf(tot.y) + EPSF),
                             1.f / (sqrtf(tot.z) + EPSF), 1.f / (sqrtf(tot.w) + EPSF));
    }
    __syncthreads();
    float inv[4] = { inv_sh.x, inv_sh.y, inv_sh.z, inv_sh.w };
    if (z == 2) { inv[0] = inv[1] = inv[2] = inv[3] = 1.f; }

#pragma unroll
    for (int ot = 0; ot < 4; ot++) {
        float4 ov = make_float4(y[ot][0] * inv[ot], y[ot][1] * inv[ot],
                                y[ot][2] * inv[ot], y[ot][3] * inv[ot]);
        *(float4*)(out + (((size_t)b * HH + h) * NN + (t0 + ot)) * DHH + d0) = ov;
    }
}

// ---------------------------------------------------------------------------
// Gated delta-rule scan, dual-state (S + S^T), f32x2 math, bulk-staged inputs.
// One block per (b,h), 128 threads.  3-stage smem ring, 16 steps per chunk,
// ONE __syncthreads per step (double-buffered coef).
// Stage layout (floats): k[16][64] @0, q[16][64] @1024, v[16][64] @2048,
//                        a[16] @3072, b[16] @3088  -> 3104 floats / stage.
// ---------------------------------------------------------------------------
#define SC_CH    16
#define SC_STGF  3104
#define SC_BYTES 12416

__global__ __launch_bounds__(128)
void scan_kernel()
{
    const int bh = blockIdx.x;
    const int tid = threadIdx.x;

    __shared__ __align__(128) float sstg[3 * SC_STGF + 128];
    __shared__ __align__(8) unsigned long long smbar[3];

    const uint32_t sbase = smem_u32(sstg);
    const uint32_t mbase = smem_u32(smbar);
    float* coefb = sstg + 3 * SC_STGF;   // 2 x 64

    const char* kb = (const char*)g_ks + (size_t)bh * NN * DHH * 4;
    const char* qb = (const char*)g_qs + (size_t)bh * NN * DHH * 4;
    const char* vb = (const char*)g_vs + (size_t)bh * NN * DHH * 4;
    const char* ab = (const char*)g_as + (size_t)bh * NN * 4;
    const char* bbp = (const char*)g_bs + (size_t)bh * NN * 4;

    if (tid == 0) {
        MBAR_INIT(mbase, 1); MBAR_INIT(mbase + 8, 1); MBAR_INIT(mbase + 16, 1);
    }
    __syncthreads();

    if (tid == 0) {
        FENCE_ASYNC();
#pragma unroll
        for (int c = 0; c < 3; c++) {
            uint32_t st = sbase + c * SC_BYTES;
            uint32_t mb = mbase + c * 8;
            MBAR_EXPECT(mb, (uint32_t)SC_BYTES);
            bulk_ld(st,         kb  + (size_t)c * SC_CH * 256, SC_CH * 256, mb);
            bulk_ld(st + 4096,  qb  + (size_t)c * SC_CH * 256, SC_CH * 256, mb);
            bulk_ld(st + 8192,  vb  + (size_t)c * SC_CH * 256, SC_CH * 256, mb);
            bulk_ld(st + 12288, ab  + (size_t)c * SC_CH * 4,   SC_CH * 4,   mb);
            bulk_ld(st + 12352, bbp + (size_t)c * SC_CH * 4,   SC_CH * 4,   mb);
        }
    }

    if (tid < 64) {
        // ---- group 0: S rows (d = tid) ----
        const int d = tid;
        ull_t S2[32];
#pragma unroll
        for (int i = 0; i < 32; i++) S2[i] = 0ull;

        for (int t = 0; t < NN; t++) {
            const int C = t >> 4, i = t & (SC_CH - 1), s = C % 3;
            if (i == 0) MBAR_WAIT(mbase + s * 8, (C / 3) & 1);
            const float* stg = sstg + s * SC_STGF;

            const ulonglong2* kp = (const ulonglong2*)(stg + i * 64);
            ull_t kr[32];
#pragma unroll
            for (int j = 0; j < 16; j++) {
                ulonglong2 kk = kp[j];
                kr[2*j] = kk.x; kr[2*j+1] = kk.y;
            }
            ull_t a0 = 0ull, a1 = 0ull, a2 = 0ull, a3 = 0ull;
#pragma unroll
            for (int j = 0; j < 8; j++) {
                FMA2(a0, S2[4*j+0], kr[4*j+0], a0);
                FMA2(a1, S2[4*j+1], kr[4*j+1], a1);
                FMA2(a2, S2[4*j+2], kr[4*j+2], a2);
                FMA2(a3, S2[4*j+3], kr[4*j+3], a3);
            }
            float x0, y0, x1, y1, x2, y2, x3, y3;
            unpack2(a0, x0, y0); unpack2(a1, x1, y1);
            unpack2(a2, x2, y2); unpack2(a3, x3, y3);
            float sk = ((x0 + y0) + (x1 + y1)) + ((x2 + y2) + (x3 + y3));

            float vc = stg[2048 + i * 64 + d];
            float ac = stg[3072 + i];
            float bc = stg[3088 + i];
            float coef = bc * vc - ac * bc * sk;
            coefb[(t & 1) * 64 + d] = coef;
            __syncthreads();   // bar #t

            // refill freed stage (chunk C+2) once group1 passed previous chunk
            if (i == 1 && C >= 1 && tid == 0 && C + 2 < NN / SC_CH) {
                const int cl = C + 2;
                const int sl = cl % 3;
                uint32_t st = sbase + sl * SC_BYTES;
                uint32_t mb = mbase + sl * 8;
                FENCE_ASYNC();
                MBAR_EXPECT(mb, (uint32_t)SC_BYTES);
                bulk_ld(st,         kb  + (size_t)cl * SC_CH * 256, SC_CH * 256, mb);
                bulk_ld(st + 4096,  qb  + (size_t)cl * SC_CH * 256, SC_CH * 256, mb);
                bulk_ld(st + 8192,  vb  + (size_t)cl * SC_CH * 256, SC_CH * 256, mb);
                bulk_ld(st + 12288, ab  + (size_t)cl * SC_CH * 4,   SC_CH * 4,   mb);
                bulk_ld(st + 12352, bbp + (size_t)cl * SC_CH * 4,   SC_CH * 4,   mb);
            }

            ull_t av2 = pack2(ac, ac), cf2 = pack2(coef, coef);
#pragma unroll
            for (int j = 0; j < 32; j++) {
                ull_t tmp;
                MUL2(tmp, av2, S2[j]);
                FMA2(S2[j], cf2, kr[j], tmp);
            }
        }
    } else {
        // ---- group 1: S^T rows (e = tid-64) ----
        const int e = tid - 64;
        ull_t T2[32];
#pragma unroll
        for (int i = 0; i < 32; i++) T2[i] = 0ull;

        for (int t = 0; t < NN; t++) {
            const int C = t >> 4, i = t & (SC_CH - 1), s = C % 3;
            if (i == 0) MBAR_WAIT(mbase + s * 8, (C / 3) & 1);
            __syncthreads();   // bar #t

            const float* stg = sstg + s * SC_STGF;
            float ac = stg[3072 + i];
            float kc = stg[i * 64 + e];
            ull_t av2 = pack2(ac, ac), kc2 = pack2(kc, kc);
            const ulonglong2* cfp = (const ulonglong2*)(coefb + (t & 1) * 64);
            const ulonglong2* qp  = (const ulonglong2*)(stg + 1024 + i * 64);
            ull_t o0 = 0ull, o1 = 0ull, o2 = 0ull, o3 = 0ull;
#pragma unroll
            for (int j = 0; j < 16; j++) {
                ulonglong2 cf = cfp[j];
                ulonglong2 qv = qp[j];
                ull_t t0, t1, u0, u1;
                MUL2(t0, cf.x, kc2);
                FMA2(u0, av2, T2[2*j],   t0); T2[2*j]   = u0;
                MUL2(t1, cf.y, kc2);
                FMA2(u1, av2, T2[2*j+1], t1); T2[2*j+1] = u1;
                if (j & 1) { FMA2(o1, u0, qv.x, o1); FMA2(o3, u1, qv.y, o3); }
                else       { FMA2(o0, u0, qv.x, o0); FMA2(o2, u1, qv.y, o2); }
            }
            float x0, y0, x1, y1, x2, y2, x3, y3;
            unpack2(o0, x0, y0); unpack2(o1, x1, y1);
            unpack2(o2, x2, y2); unpack2(o3, x3, y3);
            float o = (((x0 + y0) + (x1 + y1)) + ((x2 + y2) + (x3 + y3)));
            // packed fp16 write: chunk = h, row m = b*NN+t, inner byte = e*2
            const int b0 = bh >> 4, h0 = bh & 15;
            size_t m = (size_t)b0 * NN + t;
            size_t off = ((size_t)h0 * MM + m) * 128 + (size_t)((e * 2) ^ (((int)m & 7) << 4));
            *(__half*)((char*)g_oh + off) = __float2half_rn(o);
        }
    }
}

// ---------------------------------------------------------------------------
// Launch (ncu capture lands on my launch index 3 -> QKV GEMM)
// ---------------------------------------------------------------------------
extern "C" void kernel_launch(void* const* d_in, const int* in_sizes, int n_in,
                              void* d_out, int out_size)
{
    (void)in_sizes; (void)n_in; (void)out_size;
    const float* x      = (const float*)d_in[0];
    const float* Wq     = (const float*)d_in[1];
    const float* bq     = (const float*)d_in[2];
    const float* Wk     = (const float*)d_in[3];
    const float* bk     = (const float*)d_in[4];
    const float* Wv     = (const float*)d_in[5];
    const float* bv     = (const float*)d_in[6];
    const float* Wa     = (const float*)d_in[7];
    const float* ba     = (const float*)d_in[8];
    const float* Wb     = (const float*)d_in[9];
    const float* bb     = (const float*)d_in[10];
    const float* conv_q = (const float*)d_in[11];
    const float* conv_k = (const float*)d_in[12];
    const float* conv_v = (const float*)d_in[13];
    const float* Wo     = (const float*)d_in[14];
    const float* bo     = (const float*)d_in[15];
    float* out = (float*)d_out;

    const int smem_big  = 1024 + 3 * (256 * 128 + 128 * 128) + 64;  // ~148.6KB
    const int smem_gate = 1024 + 2 * (128 * 128 + 32 * 128) + 64;   // ~42KB
    cudaFuncSetAttribute(hmma_big<0>, cudaFuncAttributeMaxDynamicSharedMemorySize, smem_big);
    cudaFuncSetAttribute(hmma_big<1>, cudaFuncAttributeMaxDynamicSharedMemorySize, smem_big);
    cudaFuncSetAttribute(hmma_gate,   cudaFuncAttributeMaxDynamicSharedMemorySize, smem_gate);

    // [0]: x pack
    cvt_x_pack<<<MM, 256>>>(x);
    // [1]: big weights pack
    cvt_w_pack<<<dim3(DIMM, 4), 256>>>(Wq, Wk, Wv, Wo);
    // [2]: gate weights pack
    cvt_ab_pack<<<dim3(16, 2), 256>>>(Wa, Wb);
    // [3]: merged QKV GEMM  <-- ncu capture
    hmma_big<0><<<dim3(24, 64), 256, smem_big>>>(bq, bk, bv, nullptr);
    // [4]: gates (head-major output)
    hmma_gate<<<dim3(1, 128), 256, smem_gate>>>(ba, bb);
    // [5]: conv + norm (head-major output)
    conv_norm_kernel<<<dim3(MM / 4, 3), 256>>>(conv_q, conv_k, conv_v);
    // [6]: scan (bulk-staged)
    scan_kernel<<<BB * HH, 128>>>();
    // [7]: output projection
    hmma_big<1><<<dim3(8, 64), 256, smem_big>>>(bo, nullptr, nullptr, out);
}